// round 13
// baseline (speedup 1.0000x reference)
#include <cuda_runtime.h>
#include <cuda_bf16.h>
#include <cstdint>
#include <math.h>

#define SS 3
#define BB 4
#define CC 256
#define HW 4096
#define EPSf 1e-5f

// ---------------- scratch ----------------------------------------------------
__device__ float g_pooled[BB*SS*CC];
__device__ float g_h[BB*CC];
__device__ float g_wmix[BB*SS];
__device__ float g_pb[3*SS*CC];
__device__ float g_cb[CC];
__device__ int   g_sem;
__device__ __align__(256) __nv_bfloat16 g_x_bf[SS*BB*CC*HW];
__device__ __align__(256) __nv_bfloat16 g_q [SS*BB*CC*HW];
__device__ __align__(256) __nv_bfloat16 g_k [SS*BB*CC*HW];
__device__ __align__(256) __nv_bfloat16 g_v [SS*BB*CC*HW];
__device__ __align__(256) __nv_bfloat16 g_qt[SS*BB*CC*HW];
__device__ __align__(256) __nv_bfloat16 g_kt[SS*BB*CC*HW];
__device__ __align__(256) __nv_bfloat16 g_vt[SS*BB*CC*HW];
__device__ __align__(256) __nv_bfloat16 g_o [SS*BB*CC*HW];
__device__ __align__(256) __nv_bfloat16 g_integr[BB*CC*HW];
__device__ __align__(256) __nv_bfloat16 g_y2[BB*CC*HW];
__device__ __align__(256) __nv_bfloat16 g_wq_bf [SS*CC*CC];
__device__ __align__(256) __nv_bfloat16 g_wk_bf [SS*CC*CC];
__device__ __align__(256) __nv_bfloat16 g_wv_bf [SS*CC*CC];
__device__ __align__(256) __nv_bfloat16 g_aiw_bf[3*CC*CC];
__device__ __align__(256) __nv_bfloat16 g_aow_bf[CC*CC];
__device__ __align__(256) __nv_bfloat16 g_cw_bf [CC*CC*9];   // r-major K, BN-scaled
__device__ __align__(256) __nv_bfloat16 g_w2_bf [CC*CC];

__device__ __forceinline__ float gelu_f(float x){
    return 0.5f * x * (1.0f + erff(x * 0.70710678118654752f));
}
__device__ __forceinline__ uint32_t pkbf(float lo, float hi){
    __nv_bfloat162 h = __float22bfloat162_rn(make_float2(lo, hi));
    return *(uint32_t*)&h;
}
__device__ __forceinline__ __nv_bfloat162 pk2(float lo, float hi){
    return __float22bfloat162_rn(make_float2(lo, hi));
}
__device__ __forceinline__ void mma16(float c[4], const uint32_t a[4], const uint32_t b[2]){
    asm volatile(
        "mma.sync.aligned.m16n8k16.row.col.f32.bf16.bf16.f32 "
        "{%0,%1,%2,%3}, {%4,%5,%6,%7}, {%8,%9}, {%0,%1,%2,%3};"
        : "+f"(c[0]), "+f"(c[1]), "+f"(c[2]), "+f"(c[3])
        : "r"(a[0]), "r"(a[1]), "r"(a[2]), "r"(a[3]), "r"(b[0]), "r"(b[1]));
}

#define CP16(dst, src) asm volatile("cp.async.cg.shared.global [%0], [%1], 16;" :: "r"(dst), "l"(src))
#define CP_COMMIT()    asm volatile("cp.async.commit_group;" ::: "memory")
#define CP_WAIT1()     asm volatile("cp.async.wait_group 1;" ::: "memory")
#define CP_WAIT0()     asm volatile("cp.async.wait_group 0;" ::: "memory")
#define LDSM_X4(r, addr) \
    asm volatile("ldmatrix.sync.aligned.m8n8.x4.shared.b16 {%0,%1,%2,%3}, [%4];" \
        : "=r"((r)[0]), "=r"((r)[1]), "=r"((r)[2]), "=r"((r)[3]) : "r"(addr))
#define LDSM_X4T(r, addr) \
    asm volatile("ldmatrix.sync.aligned.m8n8.x4.trans.shared.b16 {%0,%1,%2,%3}, [%4];" \
        : "=r"((r)[0]), "=r"((r)[1]), "=r"((r)[2]), "=r"((r)[3]) : "r"(addr))

// ================= 128x128 GEMM core (256 thr, occ 2) =========================
__device__ __forceinline__ void cpA(uint32_t As, const __nv_bfloat16* W, int lda, int tid){
    #pragma unroll
    for(int i = 0; i < 2; i++){
        int id = tid + i*256;
        int m = id >> 2, u = id & 3;
        const __nv_bfloat16* src = W + (size_t)m*lda + u*8;
        uint32_t unit8 = (uint32_t)((((m&1)<<2) | u) ^ ((m>>1)&7));
        CP16(As + ((m>>1)<<7) + (unit8<<4), src);
    }
}
__device__ __forceinline__ void cpB(uint32_t Bs, const __nv_bfloat16* X, size_t stride, int tid){
    #pragma unroll
    for(int i = 0; i < 2; i++){
        int id = tid + i*256;
        int k = id >> 4, u = id & 15;
        const __nv_bfloat16* src = X + (size_t)k*stride + u*8;
        CP16(Bs + (k<<8) + (((uint32_t)(u ^ (k&7)))<<4), src);
    }
}
__device__ __forceinline__ void chunk_mma(uint32_t As, uint32_t Bs, float acc[4][4][4],
                                          int warp_m, int warp_n, int lane){
    int ml = lane & 15, sel = lane >> 4;
    #pragma unroll
    for(int kb = 0; kb < 2; kb++){
        uint32_t a[4][4], bb[2][4];
        #pragma unroll
        for(int mt = 0; mt < 4; mt++){
            int m = warp_m*64 + mt*16 + ml;
            int unit = kb*2 + sel;
            uint32_t addr = As + ((m>>1)<<7) +
                ((uint32_t)(((((m&1)<<2) | unit) ^ ((m>>1)&7)))<<4);
            LDSM_X4(a[mt], addr);
        }
        #pragma unroll
        for(int np = 0; np < 2; np++){
            int kk = kb*16 + ml;
            int u = warp_n*4 + np*2 + sel;
            uint32_t addr = Bs + (kk<<8) + (((uint32_t)(u ^ (kk&7)))<<4);
            LDSM_X4T(bb[np], addr);
        }
        #pragma unroll
        for(int mt = 0; mt < 4; mt++)
            #pragma unroll
            for(int nt = 0; nt < 4; nt++)
                mma16(acc[mt][nt], a[mt], bb[nt>>1] + ((nt&1)<<1));
    }
}

#define GEMM_PRE() \
    __shared__ __align__(16) uint32_t smA[3][2048]; \
    __shared__ __align__(16) uint32_t smB[3][2048]; \
    uint32_t AsB = (uint32_t)__cvta_generic_to_shared(smA); \
    uint32_t BsB = (uint32_t)__cvta_generic_to_shared(smB); \
    float acc[4][4][4]; \
    _Pragma("unroll") \
    for(int i=0;i<4;i++) _Pragma("unroll") for(int j=0;j<4;j++) _Pragma("unroll") for(int r=0;r<4;r++) acc[i][j][r]=0.f; \
    int tid = threadIdx.x; \
    int wid = tid >> 5, lane = tid & 31; \
    int warp_m = wid >> 2, warp_n = wid & 3; \
    int g = lane >> 2, tg = lane & 3; (void)g; (void)tg;

#define GEMM_LOOP(NK, APTR, BPTR) \
    cpA(AsB,        APTR(0), lda, tid); cpB(BsB,        BPTR(0), strideB, tid); CP_COMMIT(); \
    cpA(AsB + 8192, APTR(1), lda, tid); cpB(BsB + 8192, BPTR(1), strideB, tid); CP_COMMIT(); \
    for(int it = 0; it < (NK); it++){ \
        if(it + 1 < (NK)) { CP_WAIT1(); } else { CP_WAIT0(); } \
        __syncthreads(); \
        if(it + 2 < (NK)){ \
            int st = (it+2)%3; \
            cpA(AsB + st*8192, APTR(it+2), lda, tid); \
            cpB(BsB + st*8192, BPTR(it+2), strideB, tid); \
            CP_COMMIT(); \
        } \
        int cb = it % 3; \
        chunk_mma(AsB + cb*8192, BsB + cb*8192, acc, warp_m, warp_n, lane); \
    }

// ================= 128x64 GEMM core (256 thr, occ 3) ==========================
__device__ __forceinline__ void cpB64(uint32_t Bs, const __nv_bfloat16* X, size_t stride, int tid){
    int k = tid >> 3, u = tid & 7;
    const __nv_bfloat16* src = X + (size_t)k*stride + u*8;
    CP16(Bs + (k<<7) + (((uint32_t)(u ^ (k&7)))<<4), src);
}
__device__ __forceinline__ void chunk_mma64(uint32_t As, uint32_t Bs, float acc[4][2][4],
                                            int warp_m, int warp_n, int lane){
    int ml = lane & 15, sel = lane >> 4;
    #pragma unroll
    for(int kb = 0; kb < 2; kb++){
        uint32_t a[4][4], bb[4];
        #pragma unroll
        for(int mt = 0; mt < 4; mt++){
            int m = warp_m*64 + mt*16 + ml;
            int unit = kb*2 + sel;
            uint32_t addr = As + ((m>>1)<<7) +
                ((uint32_t)(((((m&1)<<2) | unit) ^ ((m>>1)&7)))<<4);
            LDSM_X4(a[mt], addr);
        }
        {
            int kk = kb*16 + ml;
            int u = warp_n*2 + sel;
            uint32_t addr = Bs + (kk<<7) + (((uint32_t)(u ^ (kk&7)))<<4);
            LDSM_X4T(bb, addr);
        }
        #pragma unroll
        for(int mt = 0; mt < 4; mt++)
            #pragma unroll
            for(int nt = 0; nt < 2; nt++)
                mma16(acc[mt][nt], a[mt], bb + (nt<<1));
    }
}

#define GEMM64_PRE() \
    __shared__ __align__(16) uint32_t smA[3][2048]; \
    __shared__ __align__(16) uint32_t smB[3][1024]; \
    uint32_t AsB = (uint32_t)__cvta_generic_to_shared(smA); \
    uint32_t BsB = (uint32_t)__cvta_generic_to_shared(smB); \
    float acc[4][2][4]; \
    _Pragma("unroll") \
    for(int i=0;i<4;i++) _Pragma("unroll") for(int j=0;j<2;j++) _Pragma("unroll") for(int r=0;r<4;r++) acc[i][j][r]=0.f; \
    int tid = threadIdx.x; \
    int wid = tid >> 5, lane = tid & 31; \
    int warp_m = wid >> 2, warp_n = wid & 3; \
    int g = lane >> 2, tg = lane & 3; (void)g; (void)tg;

#define GEMM64_LOOP(NK, APTR, BPTR) \
    cpA(AsB,        APTR(0), lda, tid); cpB64(BsB,        BPTR(0), strideB, tid); CP_COMMIT(); \
    cpA(AsB + 8192, APTR(1), lda, tid); cpB64(BsB + 4096, BPTR(1), strideB, tid); CP_COMMIT(); \
    for(int it = 0; it < (NK); it++){ \
        if(it + 1 < (NK)) { CP_WAIT1(); } else { CP_WAIT0(); } \
        __syncthreads(); \
        if(it + 2 < (NK)){ \
            int st = (it+2)%3; \
            cpA(AsB + st*8192, APTR(it+2), lda, tid); \
            cpB64(BsB + st*4096, BPTR(it+2), strideB, tid); \
            CP_COMMIT(); \
        } \
        int cb = it % 3; \
        chunk_mma64(AsB + cb*8192, BsB + cb*4096, acc, warp_m, warp_n, lane); \
    }

// ---------------- prep: merged weight + x conversion ---------------------------
__global__ void k_cvt(const float* Wq, const float* Wk_, const float* Wv,
                      const float* aiw, const float* aow, const float* cw, const float* w2,
                      const float* bnq, const float* bnk, const float* bnv, const float* cbn,
                      const float* x){
    int bid = blockIdx.x;
    if(bid < 3072){
        // x -> bf16 + pool (one block per channel)
        int id = bid;
        int c = id & 255;
        int b = (id >> 8) & 3;
        int s = id >> 10;
        size_t base = (size_t)id * HW;
        const float4* src = (const float4*)(x + base);
        int t = threadIdx.x;
        float sum = 0.f;
        #pragma unroll
        for(int i = 0; i < 4; i++){
            int idx = t*4 + i*1024;
            float4 v = src[idx >> 2];
            sum += v.x + v.y + v.z + v.w;
            uint2 o; o.x = pkbf(v.x, v.y); o.y = pkbf(v.z, v.w);
            *(uint2*)(g_x_bf + base + idx) = o;
        }
        __shared__ float red[8];
        #pragma unroll
        for(int o = 16; o > 0; o >>= 1) sum += __shfl_down_sync(0xffffffffu, sum, o);
        if((t & 31) == 0) red[t >> 5] = sum;
        __syncthreads();
        if(t == 0){
            float tt = 0.f;
            #pragma unroll
            for(int i = 0; i < 8; i++) tt += red[i];
            g_pooled[(b*SS + s)*CC + c] = tt * (1.0f / HW);
        }
        return;
    }
    int i = ((bid - 3072)*256 + threadIdx.x) * 4;
    if(i < 589824){
        const float* src; __nv_bfloat16* dst; const float* bn; int off;
        if(i < 196608){ src=Wq; dst=g_wq_bf; bn=bnq; off=i; }
        else if(i < 393216){ src=Wk_; dst=g_wk_bf; bn=bnk; off=i-196608; }
        else { src=Wv; dst=g_wv_bf; bn=bnv; off=i-393216; }
        int s = off >> 16, o = (off >> 8) & 255;
        float sc = bn[(s*4+0)*CC+o] * rsqrtf(bn[(s*4+3)*CC+o] + EPSf);
        float4 v = *(const float4*)(src + off);
        uint2 ov; ov.x = pkbf(v.x*sc, v.y*sc); ov.y = pkbf(v.z*sc, v.w*sc);
        *(uint2*)(dst + off) = ov;
        return;
    }
    if(i < 786432){
        int off = i - 589824;
        float4 v = *(const float4*)(aiw + off);
        uint2 ov; ov.x = pkbf(v.x, v.y); ov.y = pkbf(v.z, v.w);
        *(uint2*)(g_aiw_bf + off) = ov;
        return;
    }
    if(i < 851968){
        int off = i - 786432;
        float4 v = *(const float4*)(aow + off);
        uint2 ov; ov.x = pkbf(v.x, v.y); ov.y = pkbf(v.z, v.w);
        *(uint2*)(g_aow_bf + off) = ov;
        return;
    }
    if(i < 1441792){
        int o4 = i - 851968;
        float4 v = *(const float4*)(cw + o4);
        float vv[4] = {v.x, v.y, v.z, v.w};
        #pragma unroll
        for(int j = 0; j < 4; j++){
            int o = o4 + j;
            int mm = o / 2304;
            int rem = o - mm*2304;
            int c = rem / 9;
            int r = rem - c*9;
            float scl = cbn[0*CC+mm] * rsqrtf(cbn[3*CC+mm] + EPSf);
            g_cw_bf[mm*2304 + r*256 + c] = __float2bfloat16(vv[j] * scl);
        }
        return;
    }
    if(i < 1507328){
        int off = i - 1441792;
        float4 v = *(const float4*)(w2 + off);
        uint2 ov; ov.x = pkbf(v.x, v.y); ov.y = pkbf(v.z, v.w);
        *(uint2*)(g_w2_bf + off) = ov;
        return;
    }
}

__global__ void k_fold(const float* bq, const float* bnq, const float* bk_, const float* bnk,
                       const float* bv, const float* bnv, const float* cb1, const float* cbn){
    int t = threadIdx.x;
    #pragma unroll
    for(int ws = 0; ws < 9; ws++){
        int which = ws / 3, s = ws - which*3;
        const float* bias = which==0 ? bq : (which==1 ? bk_ : bv);
        const float* bn   = which==0 ? bnq : (which==1 ? bnk : bnv);
        float sc = bn[(s*4+0)*CC+t] * rsqrtf(bn[(s*4+3)*CC+t] + EPSf);
        g_pb[(which*SS+s)*CC+t] = (bias[s*CC+t] - bn[(s*4+2)*CC+t])*sc + bn[(s*4+1)*CC+t];
    }
    float sc = cbn[0*CC+t] * rsqrtf(cbn[3*CC+t] + EPSf);
    g_cb[t] = (cb1[t] - cbn[2*CC+t])*sc + cbn[1*CC+t];
}

// ---------------- importance MLP (fused) ---------------------------------------
__global__ void k_imp(const float* __restrict__ iw1, const float* __restrict__ ib1,
                      const float* __restrict__ iw2, const float* __restrict__ ib2){
    int warp = (blockIdx.x * 256 + threadIdx.x) >> 5;
    int lane = threadIdx.x & 31;
    const float* row = iw1 + (size_t)warp * (SS*CC);
    float a0=0.f, a1=0.f, a2=0.f, a3=0.f;
    for(int i = lane; i < SS*CC; i += 32){
        float w = row[i];
        a0 += w * g_pooled[0*(SS*CC)+i];
        a1 += w * g_pooled[1*(SS*CC)+i];
        a2 += w * g_pooled[2*(SS*CC)+i];
        a3 += w * g_pooled[3*(SS*CC)+i];
    }
    #pragma unroll
    for(int o = 16; o > 0; o >>= 1){
        a0 += __shfl_down_sync(0xffffffffu, a0, o);
        a1 += __shfl_down_sync(0xffffffffu, a1, o);
        a2 += __shfl_down_sync(0xffffffffu, a2, o);
        a3 += __shfl_down_sync(0xffffffffu, a3, o);
    }
    if(lane == 0){
        float bi = ib1[warp];
        g_h[0*CC+warp] = gelu_f(a0 + bi);
        g_h[1*CC+warp] = gelu_f(a1 + bi);
        g_h[2*CC+warp] = gelu_f(a2 + bi);
        g_h[3*CC+warp] = gelu_f(a3 + bi);
    }
    __shared__ int isLast;
    __shared__ float lg[12];
    if(threadIdx.x == 0){
        __threadfence();
        int v = atomicAdd(&g_sem, 1);
        isLast = (v == (int)gridDim.x - 1);
        if(isLast) g_sem = 0;
    }
    __syncthreads();
    if(!isLast) return;
    __threadfence();
    int w = threadIdx.x >> 5;
    #pragma unroll
    for(int rep = 0; rep < 2; rep++){
        int pair = w + rep*8;
        if(pair < 12){
            int b = pair / SS, s = pair - b*SS;
            float acc = 0.f;
            for(int c = lane; c < CC; c += 32) acc += g_h[b*CC+c] * iw2[s*CC + c];
            #pragma unroll
            for(int o = 16; o > 0; o >>= 1) acc += __shfl_down_sync(0xffffffffu, acc, o);
            if(lane == 0) lg[pair] = acc + ib2[s];
        }
    }
    __syncthreads();
    if(threadIdx.x < BB){
        int bb = threadIdx.x;
        float l0 = lg[bb*3+0], l1 = lg[bb*3+1], l2 = lg[bb*3+2];
        float m  = fmaxf(l0, fmaxf(l1, l2));
        float e0 = expf(l0-m), e1 = expf(l1-m), e2 = expf(l2-m);
        float inv = 1.0f / (e0 + e1 + e2);
        g_wmix[bb*SS+0] = e0*inv; g_wmix[bb*SS+1] = e1*inv; g_wmix[bb*SS+2] = e2*inv;
    }
}

// ---------------- stage 3: q/k/v projection (folded BN) ------------------------
__global__ __launch_bounds__(256,2) void k_projT()
{
    int z = blockIdx.z;
    int which = z / 12;
    int s = (z % 12) >> 2;
    int b = z & 3;
    const __nv_bfloat16* W; __nv_bfloat16* out;
    if(which == 0){ W = g_wq_bf; out = g_q; }
    else if(which == 1){ W = g_wk_bf; out = g_k; }
    else { W = g_wv_bf; out = g_v; }
    W += s * CC * CC;
    const float* pb = g_pb + (which*SS+s)*CC;
    const __nv_bfloat16* X = g_x_bf + (size_t)(s*BB+b)*CC*HW;
    __nv_bfloat16*       O = out    + (size_t)(s*BB+b)*CC*HW;
    int m0 = blockIdx.y * 128;
    int n0 = blockIdx.x * 128;
    int lda = CC; size_t strideB = HW;

    GEMM_PRE();
    #define APTR(it) (W + (size_t)m0*CC + (it)*32)
    #define BPTR(it) (X + (size_t)(it)*32*HW + n0)
    GEMM_LOOP(8, APTR, BPTR)
    #undef APTR
    #undef BPTR
    #pragma unroll
    for(int mi = 0; mi < 4; mi++){
        int r0 = m0 + warp_m*64 + mi*16 + g;
        int r1 = r0 + 8;
        float bi0 = pb[r0], bi1 = pb[r1];
        #pragma unroll
        for(int ni = 0; ni < 4; ni++){
            int nc = n0 + warp_n*32 + ni*8 + tg*2;
            *(__nv_bfloat162*)&O[(size_t)r0*HW + nc] =
                pk2(gelu_f(acc[mi][ni][0] + bi0), gelu_f(acc[mi][ni][1] + bi0));
            *(__nv_bfloat162*)&O[(size_t)r1*HW + nc] =
                pk2(gelu_f(acc[mi][ni][2] + bi1), gelu_f(acc[mi][ni][3] + bi1));
        }
    }
}

// ---------------- stage 4: attn_in projection ----------------------------------
__global__ __launch_bounds__(256,2) void k_attninT(const float* __restrict__ aib)
{
    int z = blockIdx.z;
    int which = z / 12;
    int s = (z % 12) >> 2;
    int b = z & 3;
    const __nv_bfloat16* W = g_aiw_bf + which * CC * CC;
    const float* bias = aib + which * CC;
    const __nv_bfloat16* Xg; __nv_bfloat16* Og;
    if(which == 0){ Xg = g_q; Og = g_qt; }
    else if(which == 1){ Xg = g_k; Og = g_kt; }
    else { Xg = g_v; Og = g_vt; }
    const __nv_bfloat16* X = Xg + (size_t)(s*BB+b)*CC*HW;
    __nv_bfloat16*       O = Og + (size_t)(s*BB+b)*CC*HW;
    int m0 = blockIdx.y * 128;
    int n0 = blockIdx.x * 128;
    int lda = CC; size_t strideB = HW;

    GEMM_PRE();
    #define APTR(it) (W + (size_t)m0*CC + (it)*32)
    #define BPTR(it) (X + (size_t)(it)*32*HW + n0)
    GEMM_LOOP(8, APTR, BPTR)
    #undef APTR
    #undef BPTR
    #pragma unroll
    for(int mi = 0; mi < 4; mi++){
        int r0 = m0 + warp_m*64 + mi*16 + g;
        int r1 = r0 + 8;
        float bi0 = bias[r0], bi1 = bias[r1];
        #pragma unroll
        for(int ni = 0; ni < 4; ni++){
            int nc = n0 + warp_n*32 + ni*8 + tg*2;
            *(__nv_bfloat162*)&O[(size_t)r0*HW + nc] =
                pk2(acc[mi][ni][0] + bi0, acc[mi][ni][1] + bi0);
            *(__nv_bfloat162*)&O[(size_t)r1*HW + nc] =
                pk2(acc[mi][ni][2] + bi1, acc[mi][ni][3] + bi1);
        }
    }
}

// ---------------- attention over S=3, 4 px/thread (+ wmix fold) ----------------
__global__ void k_attn(){
    int idx = blockIdx.x * blockDim.x + threadIdx.x;
    int head = blockIdx.y;
    int b = idx >> 10;
    int p = (idx & 1023) * 4;
    int off0 = ((0*BB+b)*CC)*HW + p;
    int off1 = ((1*BB+b)*CC)*HW + p;
    int off2 = ((2*BB+b)*CC)*HW + p;
    int cbase = head * 32;

    float sc[3][3][4];
    #pragma unroll
    for(int i=0;i<3;i++)
        #pragma unroll
        for(int j=0;j<3;j++)
            #pragma unroll
            for(int e=0;e<4;e++) sc[i][j][e]=0.f;

    #pragma unroll 4
    for(int d = 0; d < 32; d++){
        int co = (cbase + d) * HW;
        float q[3][4], k[3][4];
        #pragma unroll
        for(int s_=0;s_<3;s_++){
            int off = (s_==0?off0:(s_==1?off1:off2)) + co;
            uint2 qv = *(const uint2*)&g_qt[off];
            uint2 kv = *(const uint2*)&g_kt[off];
            float2 qa = __bfloat1622float2(*(__nv_bfloat162*)&qv.x);
            float2 qb = __bfloat1622float2(*(__nv_bfloat162*)&qv.y);
            float2 ka = __bfloat1622float2(*(__nv_bfloat162*)&kv.x);
            float2 kb = __bfloat1622float2(*(__nv_bfloat162*)&kv.y);
            q[s_][0]=qa.x; q[s_][1]=qa.y; q[s_][2]=qb.x; q[s_][3]=qb.y;
            k[s_][0]=ka.x; k[s_][1]=ka.y; k[s_][2]=kb.x; k[s_][3]=kb.y;
        }
        #pragma unroll
        for(int i=0;i<3;i++)
            #pragma unroll
            for(int j=0;j<3;j++)
                #pragma unroll
                for(int e=0;e<4;e++) sc[i][j][e] += q[i][e]*k[j][e];
    }
    const float scale = 0.17677669529663688f;
    float at[3][3][4];
    #pragma unroll
    for(int s_ = 0; s_ < 3; s_++){
        #pragma unroll
        for(int e = 0; e < 4; e++){
            float a0 = sc[s_][0][e]*scale, a1 = sc[s_][1][e]*scale, a2 = sc[s_][2][e]*scale;
            float m = fmaxf(a0, fmaxf(a1, a2));
            float e0 = expf(a0-m), e1 = expf(a1-m), e2 = expf(a2-m);
            float inv = 1.0f / (e0+e1+e2);
            at[s_][0][e]=e0*inv; at[s_][1][e]=e1*inv; at[s_][2][e]=e2*inv;
        }
    }
    float wm[3] = { g_wmix[b*3+0], g_wmix[b*3+1], g_wmix[b*3+2] };
    #pragma unroll 4
    for(int d = 0; d < 32; d++){
        int co = (cbase + d) * HW;
        float v[3][4];
        #pragma unroll
        for(int s_=0;s_<3;s_++){
            int off = (s_==0?off0:(s_==1?off1:off2)) + co;
            uint2 vv = *(const uint2*)&g_vt[off];
            float2 va = __bfloat1622float2(*(__nv_bfloat162*)&vv.x);
            float2 vb = __bfloat1622float2(*(__nv_bfloat162*)&vv.y);
            v[s_][0]=va.x; v[s_][1]=va.y; v[s_][2]=vb.x; v[s_][3]=vb.y;
        }
        #pragma unroll
        for(int s_=0;s_<3;s_++){
            float o[4];
            #pragma unroll
            for(int e=0;e<4;e++)
                o[e] = wm[s_]*(at[s_][0][e]*v[0][e] + at[s_][1][e]*v[1][e] + at[s_][2][e]*v[2][e]);
            uint2 ov;
            ov.x = pkbf(o[0], o[1]);
            ov.y = pkbf(o[2], o[3]);
            int off = (s_==0?off0:(s_==1?off1:off2)) + co;
            *(uint2*)&g_o[off] = ov;
        }
    }
}

// ---------------- stage 6: attn_out GEMM (K=768, 128x64 tiles, occ 3) ----------
__global__ __launch_bounds__(256,3) void k_outT(const float* __restrict__ bo)
{
    int b = blockIdx.z;
    int m0 = blockIdx.y * 128;
    int n0 = blockIdx.x * 64;
    int lda = CC; size_t strideB = HW;

    GEMM64_PRE();
    #define APTR(it) (g_aow_bf + (size_t)m0*CC + (((it)*32) & 255))
    #define BPTR(it) (g_o + (size_t)(((((it)*32) >> 8)*BB + b)*CC + (((it)*32) & 255))*HW + n0)
    GEMM64_LOOP(24, APTR, BPTR)
    #undef APTR
    #undef BPTR
    #pragma unroll
    for(int mi = 0; mi < 4; mi++){
        int r0 = m0 + warp_m*64 + mi*16 + g;
        int r1 = r0 + 8;
        float bi0 = bo[r0], bi1 = bo[r1];
        #pragma unroll
        for(int ni = 0; ni < 2; ni++){
            int nc = n0 + warp_n*16 + ni*8 + tg*2;
            *(__nv_bfloat162*)&g_integr[(size_t)(b*CC+r0)*HW + nc] =
                pk2(acc[mi][ni][0] + bi0, acc[mi][ni][1] + bi0);
            *(__nv_bfloat162*)&g_integr[(size_t)(b*CC+r1)*HW + nc] =
                pk2(acc[mi][ni][2] + bi1, acc[mi][ni][3] + bi1);
        }
    }
}

// ---------------- stage 7: 3x3 conv (K=2304 r-major, 128x64 tiles, occ 3) ------
__device__ __forceinline__ void gatherB_conv64(uint4* rv, int b, int it, int n0, int tid){
    int r = it >> 3;
    int c0 = (it & 7) * 32;
    int kh = (r * 11) >> 5;
    int dw = (r - kh*3) - 1;
    int dh = kh - 1;
    int krow = tid >> 3, u = tid & 7;
    const __nv_bfloat16* src = g_integr + (size_t)(b*CC + c0 + krow)*HW;
    int p0 = n0 + u*8;
    int h = p0 >> 6, w0 = p0 & 63;
    int hh = h + dh;
    uint4 out = make_uint4(0u,0u,0u,0u);
    if((unsigned)hh < 64u){
        const __nv_bfloat16* rp = src + hh*64 + w0;
        if(dw == 0){
            out = *(const uint4*)rp;
        } else if(dw > 0){
            uint4 v = *(const uint4*)rp;
            uint32_t nx = (w0 < 56) ? *(const uint32_t*)(rp + 8) : 0u;
            out.x = __byte_perm(v.x, v.y, 0x5432);
            out.y = __byte_perm(v.y, v.z, 0x5432);
            out.z = __byte_perm(v.z, v.w, 0x5432);
            out.w = __byte_perm(v.w, nx,  0x5432);
        } else {
            uint4 v = *(const uint4*)rp;
            uint32_t pv = (w0 > 0) ? *(const uint32_t*)(rp - 2) : 0u;
            out.x = __byte_perm(pv,  v.x, 0x5432);
            out.y = __byte_perm(v.x, v.y, 0x5432);
            out.z = __byte_perm(v.y, v.z, 0x5432);
            out.w = __byte_perm(v.z, v.w, 0x5432);
        }
    }
    *rv = out;
}
__device__ __forceinline__ void stsB_conv64(uint32_t* smBbuf, const uint4* rv, int tid){
    int k = tid >> 3, u = tid & 7;
    int widx = k*32 + ((u ^ (k&7)) << 2);
    *(uint4*)&smBbuf[widx] = *rv;
}

__global__ __launch_bounds__(256,3) void k_convT()
{
    int b = blockIdx.z;
    int m0 = blockIdx.y * 128;
    int n0 = blockIdx.x * 64;
    const int lda = CC*9;
    const int nk = (CC*9)/32;   // 72

    GEMM64_PRE();
    cpA(AsB,        g_cw_bf + (size_t)m0*lda + 0,  lda, tid); CP_COMMIT();
    cpA(AsB + 8192, g_cw_bf + (size_t)m0*lda + 32, lda, tid); CP_COMMIT();
    {
        uint4 rv;
        gatherB_conv64(&rv, b, 0, n0, tid);
        stsB_conv64(smB[0], &rv, tid);
    }
    for(int it = 0; it < nk; it++){
        if(it + 1 < nk) { CP_WAIT1(); } else { CP_WAIT0(); }
        __syncthreads();
        if(it + 2 < nk){
            int st = (it+2)%3;
            cpA(AsB + st*8192, g_cw_bf + (size_t)m0*lda + (it+2)*32, lda, tid);
            CP_COMMIT();
        }
        uint4 rv;
        if(it + 1 < nk) gatherB_conv64(&rv, b, it+1, n0, tid);
        int cb = it % 3;
        chunk_mma64(AsB + cb*8192, BsB + cb*4096, acc, warp_m, warp_n, lane);
        if(it + 1 < nk) stsB_conv64(smB[(it+1)%3], &rv, tid);
    }
    #pragma unroll
    for(int mi = 0; mi < 4; mi++){
        int r0 = m0 + warp_m*64 + mi*16 + g;
        int r1 = r0 + 8;
        float bi0 = g_cb[r0], bi1 = g_cb[r1];
        #pragma unroll
        for(int ni = 0; ni < 2; ni++){
            int nc = n0 + warp_n*16 + ni*8 + tg*2;
            *(__nv_bfloat162*)&g_y2[(size_t)(b*CC+r0)*HW + nc] =
                pk2(gelu_f(acc[mi][ni][0] + bi0), gelu_f(acc[mi][ni][1] + bi0));
            *(__nv_bfloat162*)&g_y2[(size_t)(b*CC+r1)*HW + nc] =
                pk2(gelu_f(acc[mi][ni][2] + bi1), gelu_f(acc[mi][ni][3] + bi1));
        }
    }
}

// ---------------- stage 8: final 1x1 + residual (128x64 tiles, occ 3) ----------
__global__ __launch_bounds__(256,3) void k_finalT(const float* __restrict__ b2,
                                                  const float* __restrict__ x,
                                                  float* __restrict__ out)
{
    int b = blockIdx.z;
    int m0 = blockIdx.y * 128;
    int n0 = blockIdx.x * 64;
    int lda = CC; size_t strideB = HW;

    GEMM64_PRE();
    #define APTR(it) (g_w2_bf + (size_t)m0*CC + (it)*32)
    #define BPTR(it) (g_y2 + (size_t)(b*CC + (it)*32)*HW + n0)
    GEMM64_LOOP(8, APTR, BPTR)
    #undef APTR
    #undef BPTR
    #pragma unroll
    for(int mi = 0; mi < 4; mi++){
        int r0 = m0 + warp_m*64 + mi*16 + g;
        int r1 = r0 + 8;
        float bi0 = b2[r0], bi1 = b2[r1];
        const float* res0 = x + (size_t)((1*BB+b)*CC + r0)*HW;
        const float* res1 = x + (size_t)((1*BB+b)*CC + r1)*HW;
        #pragma unroll
        for(int ni = 0; ni < 2; ni++){
            int nc = n0 + warp_n*16 + ni*8 + tg*2;
            float2 a0 = *(const float2*)&res0[nc];
            float2 a1 = *(const float2*)&res1[nc];
            float2 o0, o1;
            o0.x = acc[mi][ni][0] + bi0 + a0.x; o0.y = acc[mi][ni][1] + bi0 + a0.y;
            o1.x = acc[mi][ni][2] + bi1 + a1.x; o1.y = acc[mi][ni][3] + bi1 + a1.y;
            *(float2*)&out[(size_t)(b*CC+r0)*HW + nc] = o0;
            *(float2*)&out[(size_t)(b*CC+r1)*HW + nc] = o1;
        }
    }
}

// ---------------- launcher ------------------------------------------------------
extern "C" void kernel_launch(void* const* d_in, const int* in_sizes, int n_in,
                              void* d_out, int out_size)
{
    (void)in_sizes; (void)n_in; (void)out_size;
    const float* x   = (const float*)d_in[0];
    const float* Wq  = (const float*)d_in[1];
    const float* bq  = (const float*)d_in[2];
    const float* bnq = (const float*)d_in[3];
    const float* Wk_ = (const float*)d_in[4];
    const float* bk_ = (const float*)d_in[5];
    const float* bnk = (const float*)d_in[6];
    const float* Wv  = (const float*)d_in[7];
    const float* bv  = (const float*)d_in[8];
    const float* bnv = (const float*)d_in[9];
    const float* iw1 = (const float*)d_in[10];
    const float* ib1 = (const float*)d_in[11];
    const float* iw2 = (const float*)d_in[12];
    const float* ib2 = (const float*)d_in[13];
    const float* aiw = (const float*)d_in[14];
    const float* aib = (const float*)d_in[15];
    const float* aow = (const float*)d_in[16];
    const float* aob = (const float*)d_in[17];
    const float* cw  = (const float*)d_in[18];
    const float* cb1 = (const float*)d_in[19];
    const float* cbn = (const float*)d_in[20];
    const float* w2  = (const float*)d_in[21];
    const float* b2  = (const float*)d_in[22];
    float* out = (float*)d_out;

    k_cvt<<<3072 + 1472, 256>>>(Wq, Wk_, Wv, aiw, aow, cw, w2, bnq, bnk, bnv, cbn, x);
    k_fold<<<1, 256>>>(bq, bnq, bk_, bnk, bv, bnv, cb1, cbn);
    k_imp<<<32, 256>>>(iw1, ib1, iw2, ib2);
    k_projT<<<dim3(32,2,36), 256>>>();
    k_attninT<<<dim3(32,2,36), 256>>>(aib);
    k_attn<<<dim3(32,8), 128>>>();
    k_outT<<<dim3(64,2,4), 256>>>(aob);
    k_convT<<<dim3(64,2,4), 256>>>();
    k_finalT<<<dim3(64,2,4), 256>>>(b2, x, out);
}

// round 15
// speedup vs baseline: 1.1055x; 1.1055x over previous
#include <cuda_runtime.h>
#include <cuda_bf16.h>
#include <cstdint>
#include <math.h>

#define SS 3
#define BB 4
#define CC 256
#define HW 4096
#define EPSf 1e-5f

// ---------------- scratch ----------------------------------------------------
__device__ float g_pooled[BB*SS*CC];
__device__ float g_h[BB*CC];
__device__ float g_wmix[BB*SS];
__device__ float g_pb[3*SS*CC];
__device__ float g_cb[CC];
__device__ int   g_sem;
__device__ __align__(256) __nv_bfloat16 g_x_bf[SS*BB*CC*HW];
__device__ __align__(256) __nv_bfloat16 g_q [SS*BB*CC*HW];
__device__ __align__(256) __nv_bfloat16 g_k [SS*BB*CC*HW];
__device__ __align__(256) __nv_bfloat16 g_v [SS*BB*CC*HW];
__device__ __align__(256) __nv_bfloat16 g_qt[SS*BB*CC*HW];
__device__ __align__(256) __nv_bfloat16 g_kt[SS*BB*CC*HW];
__device__ __align__(256) __nv_bfloat16 g_vt[SS*BB*CC*HW];
__device__ __align__(256) __nv_bfloat16 g_o [SS*BB*CC*HW];
__device__ __align__(256) __nv_bfloat16 g_integr[BB*CC*HW];
__device__ __align__(256) __nv_bfloat16 g_y2[BB*CC*HW];
__device__ __align__(256) __nv_bfloat16 g_wq_bf [SS*CC*CC];
__device__ __align__(256) __nv_bfloat16 g_wk_bf [SS*CC*CC];
__device__ __align__(256) __nv_bfloat16 g_wv_bf [SS*CC*CC];
__device__ __align__(256) __nv_bfloat16 g_aiw_bf[3*CC*CC];
__device__ __align__(256) __nv_bfloat16 g_aow_bf[CC*CC];
__device__ __align__(256) __nv_bfloat16 g_cw_bf [CC*CC*9];   // r-major K, BN-scaled
__device__ __align__(256) __nv_bfloat16 g_w2_bf [CC*CC];

__device__ __forceinline__ float gelu_f(float x){
    return 0.5f * x * (1.0f + erff(x * 0.70710678118654752f));
}
__device__ __forceinline__ uint32_t pkbf(float lo, float hi){
    __nv_bfloat162 h = __float22bfloat162_rn(make_float2(lo, hi));
    return *(uint32_t*)&h;
}
__device__ __forceinline__ __nv_bfloat162 pk2(float lo, float hi){
    return __float22bfloat162_rn(make_float2(lo, hi));
}
__device__ __forceinline__ void mma16(float c[4], const uint32_t a[4], const uint32_t b[2]){
    asm volatile(
        "mma.sync.aligned.m16n8k16.row.col.f32.bf16.bf16.f32 "
        "{%0,%1,%2,%3}, {%4,%5,%6,%7}, {%8,%9}, {%0,%1,%2,%3};"
        : "+f"(c[0]), "+f"(c[1]), "+f"(c[2]), "+f"(c[3])
        : "r"(a[0]), "r"(a[1]), "r"(a[2]), "r"(a[3]), "r"(b[0]), "r"(b[1]));
}

#define CP16(dst, src) asm volatile("cp.async.cg.shared.global [%0], [%1], 16;" :: "r"(dst), "l"(src))
#define CP_COMMIT()    asm volatile("cp.async.commit_group;" ::: "memory")
#define CP_WAIT1()     asm volatile("cp.async.wait_group 1;" ::: "memory")
#define CP_WAIT0()     asm volatile("cp.async.wait_group 0;" ::: "memory")
#define LDSM_X4(r, addr) \
    asm volatile("ldmatrix.sync.aligned.m8n8.x4.shared.b16 {%0,%1,%2,%3}, [%4];" \
        : "=r"((r)[0]), "=r"((r)[1]), "=r"((r)[2]), "=r"((r)[3]) : "r"(addr))
#define LDSM_X4T(r, addr) \
    asm volatile("ldmatrix.sync.aligned.m8n8.x4.trans.shared.b16 {%0,%1,%2,%3}, [%4];" \
        : "=r"((r)[0]), "=r"((r)[1]), "=r"((r)[2]), "=r"((r)[3]) : "r"(addr))

// ================= 128x128 GEMM core (256 thr, occ 2) — R9 config =============
__device__ __forceinline__ void cpA(uint32_t As, const __nv_bfloat16* W, int lda, int tid){
    #pragma unroll
    for(int i = 0; i < 2; i++){
        int id = tid + i*256;
        int m = id >> 2, u = id & 3;
        const __nv_bfloat16* src = W + (size_t)m*lda + u*8;
        uint32_t unit8 = (uint32_t)((((m&1)<<2) | u) ^ ((m>>1)&7));
        CP16(As + ((m>>1)<<7) + (unit8<<4), src);
    }
}
__device__ __forceinline__ void cpB(uint32_t Bs, const __nv_bfloat16* X, size_t stride, int tid){
    #pragma unroll
    for(int i = 0; i < 2; i++){
        int id = tid + i*256;
        int k = id >> 4, u = id & 15;
        const __nv_bfloat16* src = X + (size_t)k*stride + u*8;
        CP16(Bs + (k<<8) + (((uint32_t)(u ^ (k&7)))<<4), src);
    }
}
__device__ __forceinline__ void chunk_mma(uint32_t As, uint32_t Bs, float acc[4][4][4],
                                          int warp_m, int warp_n, int lane){
    int ml = lane & 15, sel = lane >> 4;
    #pragma unroll
    for(int kb = 0; kb < 2; kb++){
        uint32_t a[4][4], bb[2][4];
        #pragma unroll
        for(int mt = 0; mt < 4; mt++){
            int m = warp_m*64 + mt*16 + ml;
            int unit = kb*2 + sel;
            uint32_t addr = As + ((m>>1)<<7) +
                ((uint32_t)(((((m&1)<<2) | unit) ^ ((m>>1)&7)))<<4);
            LDSM_X4(a[mt], addr);
        }
        #pragma unroll
        for(int np = 0; np < 2; np++){
            int kk = kb*16 + ml;
            int u = warp_n*4 + np*2 + sel;
            uint32_t addr = Bs + (kk<<8) + (((uint32_t)(u ^ (kk&7)))<<4);
            LDSM_X4T(bb[np], addr);
        }
        #pragma unroll
        for(int mt = 0; mt < 4; mt++)
            #pragma unroll
            for(int nt = 0; nt < 4; nt++)
                mma16(acc[mt][nt], a[mt], bb[nt>>1] + ((nt&1)<<1));
    }
}

#define GEMM_PRE() \
    __shared__ __align__(16) uint32_t smA[3][2048]; \
    __shared__ __align__(16) uint32_t smB[3][2048]; \
    uint32_t AsB = (uint32_t)__cvta_generic_to_shared(smA); \
    uint32_t BsB = (uint32_t)__cvta_generic_to_shared(smB); \
    float acc[4][4][4]; \
    _Pragma("unroll") \
    for(int i=0;i<4;i++) _Pragma("unroll") for(int j=0;j<4;j++) _Pragma("unroll") for(int r=0;r<4;r++) acc[i][j][r]=0.f; \
    int tid = threadIdx.x; \
    int wid = tid >> 5, lane = tid & 31; \
    int warp_m = wid >> 2, warp_n = wid & 3; \
    int g = lane >> 2, tg = lane & 3; (void)g; (void)tg;

#define GEMM_LOOP(NK, APTR, BPTR) \
    cpA(AsB,        APTR(0), lda, tid); cpB(BsB,        BPTR(0), strideB, tid); CP_COMMIT(); \
    cpA(AsB + 8192, APTR(1), lda, tid); cpB(BsB + 8192, BPTR(1), strideB, tid); CP_COMMIT(); \
    for(int it = 0; it < (NK); it++){ \
        if(it + 1 < (NK)) { CP_WAIT1(); } else { CP_WAIT0(); } \
        __syncthreads(); \
        if(it + 2 < (NK)){ \
            int st = (it+2)%3; \
            cpA(AsB + st*8192, APTR(it+2), lda, tid); \
            cpB(BsB + st*8192, BPTR(it+2), strideB, tid); \
            CP_COMMIT(); \
        } \
        int cb = it % 3; \
        chunk_mma(AsB + cb*8192, BsB + cb*8192, acc, warp_m, warp_n, lane); \
    }

// ---------------- prep: merged weight + x conversion ---------------------------
__global__ void k_cvt(const float* Wq, const float* Wk_, const float* Wv,
                      const float* aiw, const float* aow, const float* cw, const float* w2,
                      const float* bnq, const float* bnk, const float* bnv, const float* cbn,
                      const float* x){
    int bid = blockIdx.x;
    if(bid < 3072){
        int id = bid;
        int c = id & 255;
        int b = (id >> 8) & 3;
        int s = id >> 10;
        size_t base = (size_t)id * HW;
        const float4* src = (const float4*)(x + base);
        int t = threadIdx.x;
        float sum = 0.f;
        #pragma unroll
        for(int i = 0; i < 4; i++){
            int idx = t*4 + i*1024;
            float4 v = src[idx >> 2];
            sum += v.x + v.y + v.z + v.w;
            uint2 o; o.x = pkbf(v.x, v.y); o.y = pkbf(v.z, v.w);
            *(uint2*)(g_x_bf + base + idx) = o;
        }
        __shared__ float red[8];
        #pragma unroll
        for(int o = 16; o > 0; o >>= 1) sum += __shfl_down_sync(0xffffffffu, sum, o);
        if((t & 31) == 0) red[t >> 5] = sum;
        __syncthreads();
        if(t == 0){
            float tt = 0.f;
            #pragma unroll
            for(int i = 0; i < 8; i++) tt += red[i];
            g_pooled[(b*SS + s)*CC + c] = tt * (1.0f / HW);
        }
        return;
    }
    int i = ((bid - 3072)*256 + threadIdx.x) * 4;
    if(i < 589824){
        const float* src; __nv_bfloat16* dst; const float* bn; int off;
        if(i < 196608){ src=Wq; dst=g_wq_bf; bn=bnq; off=i; }
        else if(i < 393216){ src=Wk_; dst=g_wk_bf; bn=bnk; off=i-196608; }
        else { src=Wv; dst=g_wv_bf; bn=bnv; off=i-393216; }
        int s = off >> 16, o = (off >> 8) & 255;
        float sc = bn[(s*4+0)*CC+o] * rsqrtf(bn[(s*4+3)*CC+o] + EPSf);
        float4 v = *(const float4*)(src + off);
        uint2 ov; ov.x = pkbf(v.x*sc, v.y*sc); ov.y = pkbf(v.z*sc, v.w*sc);
        *(uint2*)(dst + off) = ov;
        return;
    }
    if(i < 786432){
        int off = i - 589824;
        float4 v = *(const float4*)(aiw + off);
        uint2 ov; ov.x = pkbf(v.x, v.y); ov.y = pkbf(v.z, v.w);
        *(uint2*)(g_aiw_bf + off) = ov;
        return;
    }
    if(i < 851968){
        int off = i - 786432;
        float4 v = *(const float4*)(aow + off);
        uint2 ov; ov.x = pkbf(v.x, v.y); ov.y = pkbf(v.z, v.w);
        *(uint2*)(g_aow_bf + off) = ov;
        return;
    }
    if(i < 1441792){
        int o4 = i - 851968;
        float4 v = *(const float4*)(cw + o4);
        float vv[4] = {v.x, v.y, v.z, v.w};
        #pragma unroll
        for(int j = 0; j < 4; j++){
            int o = o4 + j;
            int mm = o / 2304;
            int rem = o - mm*2304;
            int c = rem / 9;
            int r = rem - c*9;
            float scl = cbn[0*CC+mm] * rsqrtf(cbn[3*CC+mm] + EPSf);
            g_cw_bf[mm*2304 + r*256 + c] = __float2bfloat16(vv[j] * scl);
        }
        return;
    }
    if(i < 1507328){
        int off = i - 1441792;
        float4 v = *(const float4*)(w2 + off);
        uint2 ov; ov.x = pkbf(v.x, v.y); ov.y = pkbf(v.z, v.w);
        *(uint2*)(g_w2_bf + off) = ov;
        return;
    }
}

__global__ void k_fold(const float* bq, const float* bnq, const float* bk_, const float* bnk,
                       const float* bv, const float* bnv, const float* cb1, const float* cbn){
    int t = threadIdx.x;
    #pragma unroll
    for(int ws = 0; ws < 9; ws++){
        int which = ws / 3, s = ws - which*3;
        const float* bias = which==0 ? bq : (which==1 ? bk_ : bv);
        const float* bn   = which==0 ? bnq : (which==1 ? bnk : bnv);
        float sc = bn[(s*4+0)*CC+t] * rsqrtf(bn[(s*4+3)*CC+t] + EPSf);
        g_pb[(which*SS+s)*CC+t] = (bias[s*CC+t] - bn[(s*4+2)*CC+t])*sc + bn[(s*4+1)*CC+t];
    }
    float sc = cbn[0*CC+t] * rsqrtf(cbn[3*CC+t] + EPSf);
    g_cb[t] = (cb1[t] - cbn[2*CC+t])*sc + cbn[1*CC+t];
}

// ---------------- importance MLP (fused, vectorized loads) ---------------------
__global__ void k_imp(const float* __restrict__ iw1, const float* __restrict__ ib1,
                      const float* __restrict__ iw2, const float* __restrict__ ib2){
    __shared__ float sp[BB*SS*CC];   // pooled, 12KB
    int t = threadIdx.x;
    #pragma unroll
    for(int i = 0; i < 12; i++) sp[t + i*256] = g_pooled[t + i*256];
    __syncthreads();

    int warp = (blockIdx.x * 256 + t) >> 5;     // 0..255
    int lane = t & 31;
    const float4* row4 = (const float4*)(iw1 + (size_t)warp * (SS*CC));
    float a0=0.f, a1=0.f, a2=0.f, a3=0.f;
    #pragma unroll
    for(int j = 0; j < 6; j++){
        float4 w = row4[lane + j*32];
        int base = (lane + j*32) * 4;
        const float* p0 = sp + 0*(SS*CC) + base;
        const float* p1 = sp + 1*(SS*CC) + base;
        const float* p2 = sp + 2*(SS*CC) + base;
        const float* p3 = sp + 3*(SS*CC) + base;
        a0 += w.x*p0[0] + w.y*p0[1] + w.z*p0[2] + w.w*p0[3];
        a1 += w.x*p1[0] + w.y*p1[1] + w.z*p1[2] + w.w*p1[3];
        a2 += w.x*p2[0] + w.y*p2[1] + w.z*p2[2] + w.w*p2[3];
        a3 += w.x*p3[0] + w.y*p3[1] + w.z*p3[2] + w.w*p3[3];
    }
    #pragma unroll
    for(int o = 16; o > 0; o >>= 1){
        a0 += __shfl_down_sync(0xffffffffu, a0, o);
        a1 += __shfl_down_sync(0xffffffffu, a1, o);
        a2 += __shfl_down_sync(0xffffffffu, a2, o);
        a3 += __shfl_down_sync(0xffffffffu, a3, o);
    }
    if(lane == 0){
        float bi = ib1[warp];
        g_h[0*CC+warp] = gelu_f(a0 + bi);
        g_h[1*CC+warp] = gelu_f(a1 + bi);
        g_h[2*CC+warp] = gelu_f(a2 + bi);
        g_h[3*CC+warp] = gelu_f(a3 + bi);
    }
    __shared__ int isLast;
    __shared__ float lg[12];
    if(t == 0){
        __threadfence();
        int v = atomicAdd(&g_sem, 1);
        isLast = (v == (int)gridDim.x - 1);
        if(isLast) g_sem = 0;
    }
    __syncthreads();
    if(!isLast) return;
    __threadfence();
    int w = t >> 5;
    #pragma unroll
    for(int rep = 0; rep < 2; rep++){
        int pair = w + rep*8;
        if(pair < 12){
            int b = pair / SS, s = pair - b*SS;
            float acc = 0.f;
            for(int c = lane; c < CC; c += 32) acc += g_h[b*CC+c] * iw2[s*CC + c];
            #pragma unroll
            for(int o = 16; o > 0; o >>= 1) acc += __shfl_down_sync(0xffffffffu, acc, o);
            if(lane == 0) lg[pair] = acc + ib2[s];
        }
    }
    __syncthreads();
    if(t < BB){
        int bb = t;
        float l0 = lg[bb*3+0], l1 = lg[bb*3+1], l2 = lg[bb*3+2];
        float m  = fmaxf(l0, fmaxf(l1, l2));
        float e0 = expf(l0-m), e1 = expf(l1-m), e2 = expf(l2-m);
        float inv = 1.0f / (e0 + e1 + e2);
        g_wmix[bb*SS+0] = e0*inv; g_wmix[bb*SS+1] = e1*inv; g_wmix[bb*SS+2] = e2*inv;
    }
}

// ---------------- stage 3: q/k/v projection (folded BN) ------------------------
__global__ __launch_bounds__(256,2) void k_projT()
{
    int z = blockIdx.z;
    int which = z / 12;
    int s = (z % 12) >> 2;
    int b = z & 3;
    const __nv_bfloat16* W; __nv_bfloat16* out;
    if(which == 0){ W = g_wq_bf; out = g_q; }
    else if(which == 1){ W = g_wk_bf; out = g_k; }
    else { W = g_wv_bf; out = g_v; }
    W += s * CC * CC;
    const float* pb = g_pb + (which*SS+s)*CC;
    const __nv_bfloat16* X = g_x_bf + (size_t)(s*BB+b)*CC*HW;
    __nv_bfloat16*       O = out    + (size_t)(s*BB+b)*CC*HW;
    int m0 = blockIdx.y * 128;
    int n0 = blockIdx.x * 128;
    int lda = CC; size_t strideB = HW;

    GEMM_PRE();
    #define APTR(it) (W + (size_t)m0*CC + (it)*32)
    #define BPTR(it) (X + (size_t)(it)*32*HW + n0)
    GEMM_LOOP(8, APTR, BPTR)
    #undef APTR
    #undef BPTR
    #pragma unroll
    for(int mi = 0; mi < 4; mi++){
        int r0 = m0 + warp_m*64 + mi*16 + g;
        int r1 = r0 + 8;
        float bi0 = pb[r0], bi1 = pb[r1];
        #pragma unroll
        for(int ni = 0; ni < 4; ni++){
            int nc = n0 + warp_n*32 + ni*8 + tg*2;
            *(__nv_bfloat162*)&O[(size_t)r0*HW + nc] =
                pk2(gelu_f(acc[mi][ni][0] + bi0), gelu_f(acc[mi][ni][1] + bi0));
            *(__nv_bfloat162*)&O[(size_t)r1*HW + nc] =
                pk2(gelu_f(acc[mi][ni][2] + bi1), gelu_f(acc[mi][ni][3] + bi1));
        }
    }
}

// ---------------- stage 4: attn_in projection ----------------------------------
__global__ __launch_bounds__(256,2) void k_attninT(const float* __restrict__ aib)
{
    int z = blockIdx.z;
    int which = z / 12;
    int s = (z % 12) >> 2;
    int b = z & 3;
    const __nv_bfloat16* W = g_aiw_bf + which * CC * CC;
    const float* bias = aib + which * CC;
    const __nv_bfloat16* Xg; __nv_bfloat16* Og;
    if(which == 0){ Xg = g_q; Og = g_qt; }
    else if(which == 1){ Xg = g_k; Og = g_kt; }
    else { Xg = g_v; Og = g_vt; }
    const __nv_bfloat16* X = Xg + (size_t)(s*BB+b)*CC*HW;
    __nv_bfloat16*       O = Og + (size_t)(s*BB+b)*CC*HW;
    int m0 = blockIdx.y * 128;
    int n0 = blockIdx.x * 128;
    int lda = CC; size_t strideB = HW;

    GEMM_PRE();
    #define APTR(it) (W + (size_t)m0*CC + (it)*32)
    #define BPTR(it) (X + (size_t)(it)*32*HW + n0)
    GEMM_LOOP(8, APTR, BPTR)
    #undef APTR
    #undef BPTR
    #pragma unroll
    for(int mi = 0; mi < 4; mi++){
        int r0 = m0 + warp_m*64 + mi*16 + g;
        int r1 = r0 + 8;
        float bi0 = bias[r0], bi1 = bias[r1];
        #pragma unroll
        for(int ni = 0; ni < 4; ni++){
            int nc = n0 + warp_n*32 + ni*8 + tg*2;
            *(__nv_bfloat162*)&O[(size_t)r0*HW + nc] =
                pk2(acc[mi][ni][0] + bi0, acc[mi][ni][1] + bi0);
            *(__nv_bfloat162*)&O[(size_t)r1*HW + nc] =
                pk2(acc[mi][ni][2] + bi1, acc[mi][ni][3] + bi1);
        }
    }
}

// ---------------- attention over S=3, 2 px/thread (+ wmix fold) ----------------
__global__ void k_attn(){
    int idx = blockIdx.x * blockDim.x + threadIdx.x;   // 0..8191, 2 px each
    int head = blockIdx.y;
    int b = idx >> 11;
    int p = (idx << 1) & 4095;
    int off0 = ((0*BB+b)*CC)*HW + p;
    int off1 = ((1*BB+b)*CC)*HW + p;
    int off2 = ((2*BB+b)*CC)*HW + p;
    int cbase = head * 32;

    float2 sc[3][3];
    #pragma unroll
    for(int i=0;i<3;i++){
        #pragma unroll
        for(int j=0;j<3;j++){ sc[i][j].x = 0.f; sc[i][j].y = 0.f; }
    }

    #pragma unroll 4
    for(int d = 0; d < 32; d++){
        int co = (cbase + d) * HW;
        float2 q0 = __bfloat1622float2(*(const __nv_bfloat162*)&g_qt[off0+co]);
        float2 q1 = __bfloat1622float2(*(const __nv_bfloat162*)&g_qt[off1+co]);
        float2 q2 = __bfloat1622float2(*(const __nv_bfloat162*)&g_qt[off2+co]);
        float2 k0 = __bfloat1622float2(*(const __nv_bfloat162*)&g_kt[off0+co]);
        float2 k1 = __bfloat1622float2(*(const __nv_bfloat162*)&g_kt[off1+co]);
        float2 k2 = __bfloat1622float2(*(const __nv_bfloat162*)&g_kt[off2+co]);
        sc[0][0].x += q0.x*k0.x; sc[0][0].y += q0.y*k0.y;
        sc[0][1].x += q0.x*k1.x; sc[0][1].y += q0.y*k1.y;
        sc[0][2].x += q0.x*k2.x; sc[0][2].y += q0.y*k2.y;
        sc[1][0].x += q1.x*k0.x; sc[1][0].y += q1.y*k0.y;
        sc[1][1].x += q1.x*k1.x; sc[1][1].y += q1.y*k1.y;
        sc[1][2].x += q1.x*k2.x; sc[1][2].y += q1.y*k2.y;
        sc[2][0].x += q2.x*k0.x; sc[2][0].y += q2.y*k0.y;
        sc[2][1].x += q2.x*k1.x; sc[2][1].y += q2.y*k1.y;
        sc[2][2].x += q2.x*k2.x; sc[2][2].y += q2.y*k2.y;
    }
    const float scale = 0.17677669529663688f;
    float2 at[3][3];
    #pragma unroll
    for(int s_ = 0; s_ < 3; s_++){
        {
            float a0 = sc[s_][0].x*scale, a1 = sc[s_][1].x*scale, a2 = sc[s_][2].x*scale;
            float m = fmaxf(a0, fmaxf(a1, a2));
            float e0 = expf(a0-m), e1 = expf(a1-m), e2 = expf(a2-m);
            float inv = 1.0f / (e0+e1+e2);
            at[s_][0].x = e0*inv; at[s_][1].x = e1*inv; at[s_][2].x = e2*inv;
        }
        {
            float a0 = sc[s_][0].y*scale, a1 = sc[s_][1].y*scale, a2 = sc[s_][2].y*scale;
            float m = fmaxf(a0, fmaxf(a1, a2));
            float e0 = expf(a0-m), e1 = expf(a1-m), e2 = expf(a2-m);
            float inv = 1.0f / (e0+e1+e2);
            at[s_][0].y = e0*inv; at[s_][1].y = e1*inv; at[s_][2].y = e2*inv;
        }
    }
    float w0 = g_wmix[b*3+0], w1 = g_wmix[b*3+1], w2 = g_wmix[b*3+2];
    #pragma unroll 4
    for(int d = 0; d < 32; d++){
        int co = (cbase + d) * HW;
        float2 v0 = __bfloat1622float2(*(const __nv_bfloat162*)&g_vt[off0+co]);
        float2 v1 = __bfloat1622float2(*(const __nv_bfloat162*)&g_vt[off1+co]);
        float2 v2 = __bfloat1622float2(*(const __nv_bfloat162*)&g_vt[off2+co]);
        float ox0 = w0*(at[0][0].x*v0.x + at[0][1].x*v1.x + at[0][2].x*v2.x);
        float oy0 = w0*(at[0][0].y*v0.y + at[0][1].y*v1.y + at[0][2].y*v2.y);
        float ox1 = w1*(at[1][0].x*v0.x + at[1][1].x*v1.x + at[1][2].x*v2.x);
        float oy1 = w1*(at[1][0].y*v0.y + at[1][1].y*v1.y + at[1][2].y*v2.y);
        float ox2 = w2*(at[2][0].x*v0.x + at[2][1].x*v1.x + at[2][2].x*v2.x);
        float oy2 = w2*(at[2][0].y*v0.y + at[2][1].y*v1.y + at[2][2].y*v2.y);
        *(__nv_bfloat162*)&g_o[off0+co] = pk2(ox0, oy0);
        *(__nv_bfloat162*)&g_o[off1+co] = pk2(ox1, oy1);
        *(__nv_bfloat162*)&g_o[off2+co] = pk2(ox2, oy2);
    }
}

// ---------------- stage 6: attn_out GEMM (K=768, pre-scaled B) -----------------
__global__ __launch_bounds__(256,2) void k_outT(const float* __restrict__ bo)
{
    int b = blockIdx.z;
    int m0 = blockIdx.y * 128;
    int n0 = blockIdx.x * 128;
    int lda = CC; size_t strideB = HW;

    GEMM_PRE();
    #define APTR(it) (g_aow_bf + (size_t)m0*CC + (((it)*32) & 255))
    #define BPTR(it) (g_o + (size_t)(((((it)*32) >> 8)*BB + b)*CC + (((it)*32) & 255))*HW + n0)
    GEMM_LOOP(24, APTR, BPTR)
    #undef APTR
    #undef BPTR
    #pragma unroll
    for(int mi = 0; mi < 4; mi++){
        int r0 = m0 + warp_m*64 + mi*16 + g;
        int r1 = r0 + 8;
        float bi0 = bo[r0], bi1 = bo[r1];
        #pragma unroll
        for(int ni = 0; ni < 4; ni++){
            int nc = n0 + warp_n*32 + ni*8 + tg*2;
            *(__nv_bfloat162*)&g_integr[(size_t)(b*CC+r0)*HW + nc] =
                pk2(acc[mi][ni][0] + bi0, acc[mi][ni][1] + bi0);
            *(__nv_bfloat162*)&g_integr[(size_t)(b*CC+r1)*HW + nc] =
                pk2(acc[mi][ni][2] + bi1, acc[mi][ni][3] + bi1);
        }
    }
}

// ---------------- stage 7: 3x3 conv as GEMM (K=2304, r-major) ------------------
__device__ __forceinline__ void gatherB_conv(uint4 rv[2], int b, int it, int n0, int tid){
    int r = it >> 3;
    int c0 = (it & 7) * 32;
    int kh = (r * 11) >> 5;
    int dw = (r - kh*3) - 1;
    int dh = kh - 1;
    #pragma unroll
    for(int i = 0; i < 2; i++){
        int id = tid + i*256;
        int krow = id >> 4, u = id & 15;
        const __nv_bfloat16* src = g_integr + (size_t)(b*CC + c0 + krow)*HW;
        int p0 = n0 + u*8;
        int h = p0 >> 6, w0 = p0 & 63;
        int hh = h + dh;
        uint4 out = make_uint4(0u,0u,0u,0u);
        if((unsigned)hh < 64u){
            const __nv_bfloat16* rp = src + hh*64 + w0;
            if(dw == 0){
                out = *(const uint4*)rp;
            } else if(dw > 0){
                uint4 v = *(const uint4*)rp;
                uint32_t nx = (w0 < 56) ? *(const uint32_t*)(rp + 8) : 0u;
                out.x = __byte_perm(v.x, v.y, 0x5432);
                out.y = __byte_perm(v.y, v.z, 0x5432);
                out.z = __byte_perm(v.z, v.w, 0x5432);
                out.w = __byte_perm(v.w, nx,  0x5432);
            } else {
                uint4 v = *(const uint4*)rp;
                uint32_t pv = (w0 > 0) ? *(const uint32_t*)(rp - 2) : 0u;
                out.x = __byte_perm(pv,  v.x, 0x5432);
                out.y = __byte_perm(v.x, v.y, 0x5432);
                out.z = __byte_perm(v.y, v.z, 0x5432);
                out.w = __byte_perm(v.z, v.w, 0x5432);
            }
        }
        rv[i] = out;
    }
}
__device__ __forceinline__ void stsB_conv(uint32_t* smBbuf, const uint4 rv[2], int tid){
    #pragma unroll
    for(int i = 0; i < 2; i++){
        int id = tid + i*256;
        int k = id >> 4, u = id & 15;
        int widx = k*64 + ((u ^ (k&7)) << 2);
        *(uint4*)&smBbuf[widx] = rv[i];
    }
}

__global__ __launch_bounds__(256,2) void k_convT()
{
    int b = blockIdx.z;
    int m0 = blockIdx.y * 128;
    int n0 = blockIdx.x * 128;
    const int lda = CC*9;
    const int nk = (CC*9)/32;   // 72

    GEMM_PRE();
    cpA(AsB,        g_cw_bf + (size_t)m0*lda + 0,  lda, tid); CP_COMMIT();
    cpA(AsB + 8192, g_cw_bf + (size_t)m0*lda + 32, lda, tid); CP_COMMIT();
    {
        uint4 rv[2];
        gatherB_conv(rv, b, 0, n0, tid);
        stsB_conv(smB[0], rv, tid);
    }
    for(int it = 0; it < nk; it++){
        if(it + 1 < nk) { CP_WAIT1(); } else { CP_WAIT0(); }
        __syncthreads();
        if(it + 2 < nk){
            int st = (it+2)%3;
            cpA(AsB + st*8192, g_cw_bf + (size_t)m0*lda + (it+2)*32, lda, tid);
            CP_COMMIT();
        }
        uint4 rv[2];
        if(it + 1 < nk) gatherB_conv(rv, b, it+1, n0, tid);
        int cb = it % 3;
        chunk_mma(AsB + cb*8192, BsB + cb*8192, acc, warp_m, warp_n, lane);
        if(it + 1 < nk) stsB_conv(smB[(it+1)%3], rv, tid);
    }
    #pragma unroll
    for(int mi = 0; mi < 4; mi++){
        int r0 = m0 + warp_m*64 + mi*16 + g;
        int r1 = r0 + 8;
        float bi0 = g_cb[r0], bi1 = g_cb[r1];
        #pragma unroll
        for(int ni = 0; ni < 4; ni++){
            int nc = n0 + warp_n*32 + ni*8 + tg*2;
            *(__nv_bfloat162*)&g_y2[(size_t)(b*CC+r0)*HW + nc] =
                pk2(gelu_f(acc[mi][ni][0] + bi0), gelu_f(acc[mi][ni][1] + bi0));
            *(__nv_bfloat162*)&g_y2[(size_t)(b*CC+r1)*HW + nc] =
                pk2(gelu_f(acc[mi][ni][2] + bi1), gelu_f(acc[mi][ni][3] + bi1));
        }
    }
}

// ---------------- stage 8: final 1x1 + residual --------------------------------
__global__ __launch_bounds__(256,2) void k_finalT(const float* __restrict__ b2,
                                                  const float* __restrict__ x,
                                                  float* __restrict__ out)
{
    int b = blockIdx.z;
    int m0 = blockIdx.y * 128;
    int n0 = blockIdx.x * 128;
    int lda = CC; size_t strideB = HW;

    GEMM_PRE();
    #define APTR(it) (g_w2_bf + (size_t)m0*CC + (it)*32)
    #define BPTR(it) (g_y2 + (size_t)(b*CC + (it)*32)*HW + n0)
    GEMM_LOOP(8, APTR, BPTR)
    #undef APTR
    #undef BPTR
    #pragma unroll
    for(int mi = 0; mi < 4; mi++){
        int r0 = m0 + warp_m*64 + mi*16 + g;
        int r1 = r0 + 8;
        float bi0 = b2[r0], bi1 = b2[r1];
        const float* res0 = x + (size_t)((1*BB+b)*CC + r0)*HW;
        const float* res1 = x + (size_t)((1*BB+b)*CC + r1)*HW;
        #pragma unroll
        for(int ni = 0; ni < 4; ni++){
            int nc = n0 + warp_n*32 + ni*8 + tg*2;
            float2 a0 = *(const float2*)&res0[nc];
            float2 a1 = *(const float2*)&res1[nc];
            float2 o0, o1;
            o0.x = acc[mi][ni][0] + bi0 + a0.x; o0.y = acc[mi][ni][1] + bi0 + a0.y;
            o1.x = acc[mi][ni][2] + bi1 + a1.x; o1.y = acc[mi][ni][3] + bi1 + a1.y;
            *(float2*)&out[(size_t)(b*CC+r0)*HW + nc] = o0;
            *(float2*)&out[(size_t)(b*CC+r1)*HW + nc] = o1;
        }
    }
}

// ---------------- launcher ------------------------------------------------------
extern "C" void kernel_launch(void* const* d_in, const int* in_sizes, int n_in,
                              void* d_out, int out_size)
{
    (void)in_sizes; (void)n_in; (void)out_size;
    const float* x   = (const float*)d_in[0];
    const float* Wq  = (const float*)d_in[1];
    const float* bq  = (const float*)d_in[2];
    const float* bnq = (const float*)d_in[3];
    const float* Wk_ = (const float*)d_in[4];
    const float* bk_ = (const float*)d_in[5];
    const float* bnk = (const float*)d_in[6];
    const float* Wv  = (const float*)d_in[7];
    const float* bv  = (const float*)d_in[8];
    const float* bnv = (const float*)d_in[9];
    const float* iw1 = (const float*)d_in[10];
    const float* ib1 = (const float*)d_in[11];
    const float* iw2 = (const float*)d_in[12];
    const float* ib2 = (const float*)d_in[13];
    const float* aiw = (const float*)d_in[14];
    const float* aib = (const float*)d_in[15];
    const float* aow = (const float*)d_in[16];
    const float* aob = (const float*)d_in[17];
    const float* cw  = (const float*)d_in[18];
    const float* cb1 = (const float*)d_in[19];
    const float* cbn = (const float*)d_in[20];
    const float* w2  = (const float*)d_in[21];
    const float* b2  = (const float*)d_in[22];
    float* out = (float*)d_out;

    k_cvt<<<3072 + 1472, 256>>>(Wq, Wk_, Wv, aiw, aow, cw, w2, bnq, bnk, bnv, cbn, x);
    k_fold<<<1, 256>>>(bq, bnq, bk_, bnk, bv, bnv, cb1, cbn);
    k_imp<<<32, 256>>>(iw1, ib1, iw2, ib2);
    k_projT<<<dim3(32,2,36), 256>>>();
    k_attninT<<<dim3(32,2,36), 256>>>(aib);
    k_attn<<<dim3(32,8), 256>>>();
    k_outT<<<dim3(32,2,4), 256>>>(aob);
    k_convT<<<dim3(32,2,4), 256>>>();
    k_finalT<<<dim3(32,2,4), 256>>>(b2, x, out);
}

// round 16
// speedup vs baseline: 1.1348x; 1.0265x over previous
#include <cuda_runtime.h>
#include <cuda_bf16.h>
#include <cstdint>
#include <math.h>

#define SS 3
#define BB 4
#define CC 256
#define HW 4096
#define EPSf 1e-5f

// ---------------- scratch ----------------------------------------------------
__device__ float g_pooled[BB*SS*CC];
__device__ float g_h[BB*CC];
__device__ float g_wmix[BB*SS];
__device__ float g_pb[3*SS*CC];
__device__ float g_cb[CC];
__device__ int   g_sem;
__device__ __align__(256) __nv_bfloat16 g_x_bf[SS*BB*CC*HW];
__device__ __align__(256) __nv_bfloat16 g_q [SS*BB*CC*HW];
__device__ __align__(256) __nv_bfloat16 g_k [SS*BB*CC*HW];
__device__ __align__(256) __nv_bfloat16 g_v [SS*BB*CC*HW];
__device__ __align__(256) __nv_bfloat16 g_qt[SS*BB*CC*HW];
__device__ __align__(256) __nv_bfloat16 g_kt[SS*BB*CC*HW];
__device__ __align__(256) __nv_bfloat16 g_vt[SS*BB*CC*HW];
__device__ __align__(256) __nv_bfloat16 g_o [SS*BB*CC*HW];
__device__ __align__(256) __nv_bfloat16 g_integr[BB*CC*HW];
__device__ __align__(256) __nv_bfloat16 g_y2[BB*CC*HW];
__device__ __align__(256) __nv_bfloat16 g_wq_bf [SS*CC*CC];
__device__ __align__(256) __nv_bfloat16 g_wk_bf [SS*CC*CC];
__device__ __align__(256) __nv_bfloat16 g_wv_bf [SS*CC*CC];
__device__ __align__(256) __nv_bfloat16 g_aiw_bf[3*CC*CC];
__device__ __align__(256) __nv_bfloat16 g_aow_bf[CC*CC];
__device__ __align__(256) __nv_bfloat16 g_cw_bf [CC*CC*9];   // r-major K, BN-scaled
__device__ __align__(256) __nv_bfloat16 g_w2_bf [CC*CC];

__device__ __forceinline__ float gelu_f(float x){
    return 0.5f * x * (1.0f + erff(x * 0.70710678118654752f));
}
__device__ __forceinline__ uint32_t pkbf(float lo, float hi){
    __nv_bfloat162 h = __float22bfloat162_rn(make_float2(lo, hi));
    return *(uint32_t*)&h;
}
__device__ __forceinline__ __nv_bfloat162 pk2(float lo, float hi){
    return __float22bfloat162_rn(make_float2(lo, hi));
}
__device__ __forceinline__ void mma16(float c[4], const uint32_t a[4], const uint32_t b[2]){
    asm volatile(
        "mma.sync.aligned.m16n8k16.row.col.f32.bf16.bf16.f32 "
        "{%0,%1,%2,%3}, {%4,%5,%6,%7}, {%8,%9}, {%0,%1,%2,%3};"
        : "+f"(c[0]), "+f"(c[1]), "+f"(c[2]), "+f"(c[3])
        : "r"(a[0]), "r"(a[1]), "r"(a[2]), "r"(a[3]), "r"(b[0]), "r"(b[1]));
}

#define CP16(dst, src) asm volatile("cp.async.cg.shared.global [%0], [%1], 16;" :: "r"(dst), "l"(src))
#define CP_COMMIT()    asm volatile("cp.async.commit_group;" ::: "memory")
#define CP_WAIT1()     asm volatile("cp.async.wait_group 1;" ::: "memory")
#define CP_WAIT0()     asm volatile("cp.async.wait_group 0;" ::: "memory")
#define LDSM_X4(r, addr) \
    asm volatile("ldmatrix.sync.aligned.m8n8.x4.shared.b16 {%0,%1,%2,%3}, [%4];" \
        : "=r"((r)[0]), "=r"((r)[1]), "=r"((r)[2]), "=r"((r)[3]) : "r"(addr))
#define LDSM_X4T(r, addr) \
    asm volatile("ldmatrix.sync.aligned.m8n8.x4.trans.shared.b16 {%0,%1,%2,%3}, [%4];" \
        : "=r"((r)[0]), "=r"((r)[1]), "=r"((r)[2]), "=r"((r)[3]) : "r"(addr))

// ================= 128x128 GEMM core (256 thr, occ 2) =========================
__device__ __forceinline__ void cpA(uint32_t As, const __nv_bfloat16* W, int lda, int tid){
    #pragma unroll
    for(int i = 0; i < 2; i++){
        int id = tid + i*256;
        int m = id >> 2, u = id & 3;
        const __nv_bfloat16* src = W + (size_t)m*lda + u*8;
        uint32_t unit8 = (uint32_t)((((m&1)<<2) | u) ^ ((m>>1)&7));
        CP16(As + ((m>>1)<<7) + (unit8<<4), src);
    }
}
__device__ __forceinline__ void cpB(uint32_t Bs, const __nv_bfloat16* X, size_t stride, int tid){
    #pragma unroll
    for(int i = 0; i < 2; i++){
        int id = tid + i*256;
        int k = id >> 4, u = id & 15;
        const __nv_bfloat16* src = X + (size_t)k*stride + u*8;
        CP16(Bs + (k<<8) + (((uint32_t)(u ^ (k&7)))<<4), src);
    }
}
__device__ __forceinline__ void chunk_mma(uint32_t As, uint32_t Bs, float acc[4][4][4],
                                          int warp_m, int warp_n, int lane){
    int ml = lane & 15, sel = lane >> 4;
    #pragma unroll
    for(int kb = 0; kb < 2; kb++){
        uint32_t a[4][4], bb[2][4];
        #pragma unroll
        for(int mt = 0; mt < 4; mt++){
            int m = warp_m*64 + mt*16 + ml;
            int unit = kb*2 + sel;
            uint32_t addr = As + ((m>>1)<<7) +
                ((uint32_t)(((((m&1)<<2) | unit) ^ ((m>>1)&7)))<<4);
            LDSM_X4(a[mt], addr);
        }
        #pragma unroll
        for(int np = 0; np < 2; np++){
            int kk = kb*16 + ml;
            int u = warp_n*4 + np*2 + sel;
            uint32_t addr = Bs + (kk<<8) + (((uint32_t)(u ^ (kk&7)))<<4);
            LDSM_X4T(bb[np], addr);
        }
        #pragma unroll
        for(int mt = 0; mt < 4; mt++)
            #pragma unroll
            for(int nt = 0; nt < 4; nt++)
                mma16(acc[mt][nt], a[mt], bb[nt>>1] + ((nt&1)<<1));
    }
}

#define GEMM_PRE() \
    __shared__ __align__(16) uint32_t smA[3][2048]; \
    __shared__ __align__(16) uint32_t smB[3][2048]; \
    uint32_t AsB = (uint32_t)__cvta_generic_to_shared(smA); \
    uint32_t BsB = (uint32_t)__cvta_generic_to_shared(smB); \
    float acc[4][4][4]; \
    _Pragma("unroll") \
    for(int i=0;i<4;i++) _Pragma("unroll") for(int j=0;j<4;j++) _Pragma("unroll") for(int r=0;r<4;r++) acc[i][j][r]=0.f; \
    int tid = threadIdx.x; \
    int wid = tid >> 5, lane = tid & 31; \
    int warp_m = wid >> 2, warp_n = wid & 3; \
    int g = lane >> 2, tg = lane & 3; (void)g; (void)tg;

// fully-unrolled mainloop: all stage indices / addresses become compile-time
#define GEMM_LOOP(NK, APTR, BPTR) \
    cpA(AsB,        APTR(0), lda, tid); cpB(BsB,        BPTR(0), strideB, tid); CP_COMMIT(); \
    cpA(AsB + 8192, APTR(1), lda, tid); cpB(BsB + 8192, BPTR(1), strideB, tid); CP_COMMIT(); \
    _Pragma("unroll") \
    for(int it = 0; it < (NK); it++){ \
        if(it + 1 < (NK)) { CP_WAIT1(); } else { CP_WAIT0(); } \
        __syncthreads(); \
        if(it + 2 < (NK)){ \
            int st = (it+2)%3; \
            cpA(AsB + st*8192, APTR(it+2), lda, tid); \
            cpB(BsB + st*8192, BPTR(it+2), strideB, tid); \
            CP_COMMIT(); \
        } \
        int cb = it % 3; \
        chunk_mma(AsB + cb*8192, BsB + cb*8192, acc, warp_m, warp_n, lane); \
    }

// ---------------- prep: merged weight + x conversion ---------------------------
__global__ void k_cvt(const float* Wq, const float* Wk_, const float* Wv,
                      const float* aiw, const float* aow, const float* cw, const float* w2,
                      const float* bnq, const float* bnk, const float* bnv, const float* cbn,
                      const float* x){
    int bid = blockIdx.x;
    if(bid < 3072){
        int id = bid;
        int c = id & 255;
        int b = (id >> 8) & 3;
        int s = id >> 10;
        size_t base = (size_t)id * HW;
        const float4* src = (const float4*)(x + base);
        int t = threadIdx.x;
        float sum = 0.f;
        #pragma unroll
        for(int i = 0; i < 4; i++){
            int idx = t*4 + i*1024;
            float4 v = src[idx >> 2];
            sum += v.x + v.y + v.z + v.w;
            uint2 o; o.x = pkbf(v.x, v.y); o.y = pkbf(v.z, v.w);
            *(uint2*)(g_x_bf + base + idx) = o;
        }
        __shared__ float red[8];
        #pragma unroll
        for(int o = 16; o > 0; o >>= 1) sum += __shfl_down_sync(0xffffffffu, sum, o);
        if((t & 31) == 0) red[t >> 5] = sum;
        __syncthreads();
        if(t == 0){
            float tt = 0.f;
            #pragma unroll
            for(int i = 0; i < 8; i++) tt += red[i];
            g_pooled[(b*SS + s)*CC + c] = tt * (1.0f / HW);
        }
        return;
    }
    int i = ((bid - 3072)*256 + threadIdx.x) * 4;
    if(i < 589824){
        const float* src; __nv_bfloat16* dst; const float* bn; int off;
        if(i < 196608){ src=Wq; dst=g_wq_bf; bn=bnq; off=i; }
        else if(i < 393216){ src=Wk_; dst=g_wk_bf; bn=bnk; off=i-196608; }
        else { src=Wv; dst=g_wv_bf; bn=bnv; off=i-393216; }
        int s = off >> 16, o = (off >> 8) & 255;
        float sc = bn[(s*4+0)*CC+o] * rsqrtf(bn[(s*4+3)*CC+o] + EPSf);
        float4 v = *(const float4*)(src + off);
        uint2 ov; ov.x = pkbf(v.x*sc, v.y*sc); ov.y = pkbf(v.z*sc, v.w*sc);
        *(uint2*)(dst + off) = ov;
        return;
    }
    if(i < 786432){
        int off = i - 589824;
        float4 v = *(const float4*)(aiw + off);
        uint2 ov; ov.x = pkbf(v.x, v.y); ov.y = pkbf(v.z, v.w);
        *(uint2*)(g_aiw_bf + off) = ov;
        return;
    }
    if(i < 851968){
        int off = i - 786432;
        float4 v = *(const float4*)(aow + off);
        uint2 ov; ov.x = pkbf(v.x, v.y); ov.y = pkbf(v.z, v.w);
        *(uint2*)(g_aow_bf + off) = ov;
        return;
    }
    if(i < 1441792){
        int o4 = i - 851968;
        float4 v = *(const float4*)(cw + o4);
        float vv[4] = {v.x, v.y, v.z, v.w};
        #pragma unroll
        for(int j = 0; j < 4; j++){
            int o = o4 + j;
            int mm = o / 2304;
            int rem = o - mm*2304;
            int c = rem / 9;
            int r = rem - c*9;
            float scl = cbn[0*CC+mm] * rsqrtf(cbn[3*CC+mm] + EPSf);
            g_cw_bf[mm*2304 + r*256 + c] = __float2bfloat16(vv[j] * scl);
        }
        return;
    }
    if(i < 1507328){
        int off = i - 1441792;
        float4 v = *(const float4*)(w2 + off);
        uint2 ov; ov.x = pkbf(v.x, v.y); ov.y = pkbf(v.z, v.w);
        *(uint2*)(g_w2_bf + off) = ov;
        return;
    }
}

__global__ void k_fold(const float* bq, const float* bnq, const float* bk_, const float* bnk,
                       const float* bv, const float* bnv, const float* cb1, const float* cbn){
    int t = threadIdx.x;
    #pragma unroll
    for(int ws = 0; ws < 9; ws++){
        int which = ws / 3, s = ws - which*3;
        const float* bias = which==0 ? bq : (which==1 ? bk_ : bv);
        const float* bn   = which==0 ? bnq : (which==1 ? bnk : bnv);
        float sc = bn[(s*4+0)*CC+t] * rsqrtf(bn[(s*4+3)*CC+t] + EPSf);
        g_pb[(which*SS+s)*CC+t] = (bias[s*CC+t] - bn[(s*4+2)*CC+t])*sc + bn[(s*4+1)*CC+t];
    }
    float sc = cbn[0*CC+t] * rsqrtf(cbn[3*CC+t] + EPSf);
    g_cb[t] = (cb1[t] - cbn[2*CC+t])*sc + cbn[1*CC+t];
}

// ---------------- importance MLP (fused, vectorized loads) ---------------------
__global__ void k_imp(const float* __restrict__ iw1, const float* __restrict__ ib1,
                      const float* __restrict__ iw2, const float* __restrict__ ib2){
    __shared__ float sp[BB*SS*CC];
    int t = threadIdx.x;
    #pragma unroll
    for(int i = 0; i < 12; i++) sp[t + i*256] = g_pooled[t + i*256];
    __syncthreads();

    int warp = (blockIdx.x * 256 + t) >> 5;
    int lane = t & 31;
    const float4* row4 = (const float4*)(iw1 + (size_t)warp * (SS*CC));
    float a0=0.f, a1=0.f, a2=0.f, a3=0.f;
    #pragma unroll
    for(int j = 0; j < 6; j++){
        float4 w = row4[lane + j*32];
        int base = (lane + j*32) * 4;
        const float* p0 = sp + 0*(SS*CC) + base;
        const float* p1 = sp + 1*(SS*CC) + base;
        const float* p2 = sp + 2*(SS*CC) + base;
        const float* p3 = sp + 3*(SS*CC) + base;
        a0 += w.x*p0[0] + w.y*p0[1] + w.z*p0[2] + w.w*p0[3];
        a1 += w.x*p1[0] + w.y*p1[1] + w.z*p1[2] + w.w*p1[3];
        a2 += w.x*p2[0] + w.y*p2[1] + w.z*p2[2] + w.w*p2[3];
        a3 += w.x*p3[0] + w.y*p3[1] + w.z*p3[2] + w.w*p3[3];
    }
    #pragma unroll
    for(int o = 16; o > 0; o >>= 1){
        a0 += __shfl_down_sync(0xffffffffu, a0, o);
        a1 += __shfl_down_sync(0xffffffffu, a1, o);
        a2 += __shfl_down_sync(0xffffffffu, a2, o);
        a3 += __shfl_down_sync(0xffffffffu, a3, o);
    }
    if(lane == 0){
        float bi = ib1[warp];
        g_h[0*CC+warp] = gelu_f(a0 + bi);
        g_h[1*CC+warp] = gelu_f(a1 + bi);
        g_h[2*CC+warp] = gelu_f(a2 + bi);
        g_h[3*CC+warp] = gelu_f(a3 + bi);
    }
    __shared__ int isLast;
    __shared__ float lg[12];
    if(t == 0){
        __threadfence();
        int v = atomicAdd(&g_sem, 1);
        isLast = (v == (int)gridDim.x - 1);
        if(isLast) g_sem = 0;
    }
    __syncthreads();
    if(!isLast) return;
    __threadfence();
    int w = t >> 5;
    #pragma unroll
    for(int rep = 0; rep < 2; rep++){
        int pair = w + rep*8;
        if(pair < 12){
            int b = pair / SS, s = pair - b*SS;
            float acc = 0.f;
            for(int c = lane; c < CC; c += 32) acc += g_h[b*CC+c] * iw2[s*CC + c];
            #pragma unroll
            for(int o = 16; o > 0; o >>= 1) acc += __shfl_down_sync(0xffffffffu, acc, o);
            if(lane == 0) lg[pair] = acc + ib2[s];
        }
    }
    __syncthreads();
    if(t < BB){
        int bb = t;
        float l0 = lg[bb*3+0], l1 = lg[bb*3+1], l2 = lg[bb*3+2];
        float m  = fmaxf(l0, fmaxf(l1, l2));
        float e0 = expf(l0-m), e1 = expf(l1-m), e2 = expf(l2-m);
        float inv = 1.0f / (e0 + e1 + e2);
        g_wmix[bb*SS+0] = e0*inv; g_wmix[bb*SS+1] = e1*inv; g_wmix[bb*SS+2] = e2*inv;
    }
}

// ---------------- stage 3: q/k/v projection (folded BN) ------------------------
__global__ __launch_bounds__(256,2) void k_projT()
{
    int z = blockIdx.z;
    int which = z / 12;
    int s = (z % 12) >> 2;
    int b = z & 3;
    const __nv_bfloat16* W; __nv_bfloat16* out;
    if(which == 0){ W = g_wq_bf; out = g_q; }
    else if(which == 1){ W = g_wk_bf; out = g_k; }
    else { W = g_wv_bf; out = g_v; }
    W += s * CC * CC;
    const float* pb = g_pb + (which*SS+s)*CC;
    const __nv_bfloat16* X = g_x_bf + (size_t)(s*BB+b)*CC*HW;
    __nv_bfloat16*       O = out    + (size_t)(s*BB+b)*CC*HW;
    int m0 = blockIdx.y * 128;
    int n0 = blockIdx.x * 128;
    int lda = CC; size_t strideB = HW;

    GEMM_PRE();
    #define APTR(it) (W + (size_t)m0*CC + (it)*32)
    #define BPTR(it) (X + (size_t)(it)*32*HW + n0)
    GEMM_LOOP(8, APTR, BPTR)
    #undef APTR
    #undef BPTR
    #pragma unroll
    for(int mi = 0; mi < 4; mi++){
        int r0 = m0 + warp_m*64 + mi*16 + g;
        int r1 = r0 + 8;
        float bi0 = pb[r0], bi1 = pb[r1];
        #pragma unroll
        for(int ni = 0; ni < 4; ni++){
            int nc = n0 + warp_n*32 + ni*8 + tg*2;
            *(__nv_bfloat162*)&O[(size_t)r0*HW + nc] =
                pk2(gelu_f(acc[mi][ni][0] + bi0), gelu_f(acc[mi][ni][1] + bi0));
            *(__nv_bfloat162*)&O[(size_t)r1*HW + nc] =
                pk2(gelu_f(acc[mi][ni][2] + bi1), gelu_f(acc[mi][ni][3] + bi1));
        }
    }
}

// ---------------- stage 4: attn_in projection ----------------------------------
__global__ __launch_bounds__(256,2) void k_attninT(const float* __restrict__ aib)
{
    int z = blockIdx.z;
    int which = z / 12;
    int s = (z % 12) >> 2;
    int b = z & 3;
    const __nv_bfloat16* W = g_aiw_bf + which * CC * CC;
    const float* bias = aib + which * CC;
    const __nv_bfloat16* Xg; __nv_bfloat16* Og;
    if(which == 0){ Xg = g_q; Og = g_qt; }
    else if(which == 1){ Xg = g_k; Og = g_kt; }
    else { Xg = g_v; Og = g_vt; }
    const __nv_bfloat16* X = Xg + (size_t)(s*BB+b)*CC*HW;
    __nv_bfloat16*       O = Og + (size_t)(s*BB+b)*CC*HW;
    int m0 = blockIdx.y * 128;
    int n0 = blockIdx.x * 128;
    int lda = CC; size_t strideB = HW;

    GEMM_PRE();
    #define APTR(it) (W + (size_t)m0*CC + (it)*32)
    #define BPTR(it) (X + (size_t)(it)*32*HW + n0)
    GEMM_LOOP(8, APTR, BPTR)
    #undef APTR
    #undef BPTR
    #pragma unroll
    for(int mi = 0; mi < 4; mi++){
        int r0 = m0 + warp_m*64 + mi*16 + g;
        int r1 = r0 + 8;
        float bi0 = bias[r0], bi1 = bias[r1];
        #pragma unroll
        for(int ni = 0; ni < 4; ni++){
            int nc = n0 + warp_n*32 + ni*8 + tg*2;
            *(__nv_bfloat162*)&O[(size_t)r0*HW + nc] =
                pk2(acc[mi][ni][0] + bi0, acc[mi][ni][1] + bi0);
            *(__nv_bfloat162*)&O[(size_t)r1*HW + nc] =
                pk2(acc[mi][ni][2] + bi1, acc[mi][ni][3] + bi1);
        }
    }
}

// ---------------- attention over S=3, 2 px/thread (+ wmix fold) ----------------
__global__ void k_attn(){
    int idx = blockIdx.x * blockDim.x + threadIdx.x;
    int head = blockIdx.y;
    int b = idx >> 11;
    int p = (idx << 1) & 4095;
    int off0 = ((0*BB+b)*CC)*HW + p;
    int off1 = ((1*BB+b)*CC)*HW + p;
    int off2 = ((2*BB+b)*CC)*HW + p;
    int cbase = head * 32;

    float2 sc[3][3];
    #pragma unroll
    for(int i=0;i<3;i++){
        #pragma unroll
        for(int j=0;j<3;j++){ sc[i][j].x = 0.f; sc[i][j].y = 0.f; }
    }

    #pragma unroll 4
    for(int d = 0; d < 32; d++){
        int co = (cbase + d) * HW;
        float2 q0 = __bfloat1622float2(*(const __nv_bfloat162*)&g_qt[off0+co]);
        float2 q1 = __bfloat1622float2(*(const __nv_bfloat162*)&g_qt[off1+co]);
        float2 q2 = __bfloat1622float2(*(const __nv_bfloat162*)&g_qt[off2+co]);
        float2 k0 = __bfloat1622float2(*(const __nv_bfloat162*)&g_kt[off0+co]);
        float2 k1 = __bfloat1622float2(*(const __nv_bfloat162*)&g_kt[off1+co]);
        float2 k2 = __bfloat1622float2(*(const __nv_bfloat162*)&g_kt[off2+co]);
        sc[0][0].x += q0.x*k0.x; sc[0][0].y += q0.y*k0.y;
        sc[0][1].x += q0.x*k1.x; sc[0][1].y += q0.y*k1.y;
        sc[0][2].x += q0.x*k2.x; sc[0][2].y += q0.y*k2.y;
        sc[1][0].x += q1.x*k0.x; sc[1][0].y += q1.y*k0.y;
        sc[1][1].x += q1.x*k1.x; sc[1][1].y += q1.y*k1.y;
        sc[1][2].x += q1.x*k2.x; sc[1][2].y += q1.y*k2.y;
        sc[2][0].x += q2.x*k0.x; sc[2][0].y += q2.y*k0.y;
        sc[2][1].x += q2.x*k1.x; sc[2][1].y += q2.y*k1.y;
        sc[2][2].x += q2.x*k2.x; sc[2][2].y += q2.y*k2.y;
    }
    const float scale = 0.17677669529663688f;
    float2 at[3][3];
    #pragma unroll
    for(int s_ = 0; s_ < 3; s_++){
        {
            float a0 = sc[s_][0].x*scale, a1 = sc[s_][1].x*scale, a2 = sc[s_][2].x*scale;
            float m = fmaxf(a0, fmaxf(a1, a2));
            float e0 = expf(a0-m), e1 = expf(a1-m), e2 = expf(a2-m);
            float inv = 1.0f / (e0+e1+e2);
            at[s_][0].x = e0*inv; at[s_][1].x = e1*inv; at[s_][2].x = e2*inv;
        }
        {
            float a0 = sc[s_][0].y*scale, a1 = sc[s_][1].y*scale, a2 = sc[s_][2].y*scale;
            float m = fmaxf(a0, fmaxf(a1, a2));
            float e0 = expf(a0-m), e1 = expf(a1-m), e2 = expf(a2-m);
            float inv = 1.0f / (e0+e1+e2);
            at[s_][0].y = e0*inv; at[s_][1].y = e1*inv; at[s_][2].y = e2*inv;
        }
    }
    float w0 = g_wmix[b*3+0], w1 = g_wmix[b*3+1], w2 = g_wmix[b*3+2];
    #pragma unroll 4
    for(int d = 0; d < 32; d++){
        int co = (cbase + d) * HW;
        float2 v0 = __bfloat1622float2(*(const __nv_bfloat162*)&g_vt[off0+co]);
        float2 v1 = __bfloat1622float2(*(const __nv_bfloat162*)&g_vt[off1+co]);
        float2 v2 = __bfloat1622float2(*(const __nv_bfloat162*)&g_vt[off2+co]);
        float ox0 = w0*(at[0][0].x*v0.x + at[0][1].x*v1.x + at[0][2].x*v2.x);
        float oy0 = w0*(at[0][0].y*v0.y + at[0][1].y*v1.y + at[0][2].y*v2.y);
        float ox1 = w1*(at[1][0].x*v0.x + at[1][1].x*v1.x + at[1][2].x*v2.x);
        float oy1 = w1*(at[1][0].y*v0.y + at[1][1].y*v1.y + at[1][2].y*v2.y);
        float ox2 = w2*(at[2][0].x*v0.x + at[2][1].x*v1.x + at[2][2].x*v2.x);
        float oy2 = w2*(at[2][0].y*v0.y + at[2][1].y*v1.y + at[2][2].y*v2.y);
        *(__nv_bfloat162*)&g_o[off0+co] = pk2(ox0, oy0);
        *(__nv_bfloat162*)&g_o[off1+co] = pk2(ox1, oy1);
        *(__nv_bfloat162*)&g_o[off2+co] = pk2(ox2, oy2);
    }
}

// ---------------- stage 6: attn_out GEMM (K=768, pre-scaled B) -----------------
__global__ __launch_bounds__(256,2) void k_outT(const float* __restrict__ bo)
{
    int b = blockIdx.z;
    int m0 = blockIdx.y * 128;
    int n0 = blockIdx.x * 128;
    int lda = CC; size_t strideB = HW;

    GEMM_PRE();
    #define APTR(it) (g_aow_bf + (size_t)m0*CC + (((it)*32) & 255))
    #define BPTR(it) (g_o + (size_t)(((((it)*32) >> 8)*BB + b)*CC + (((it)*32) & 255))*HW + n0)
    GEMM_LOOP(24, APTR, BPTR)
    #undef APTR
    #undef BPTR
    #pragma unroll
    for(int mi = 0; mi < 4; mi++){
        int r0 = m0 + warp_m*64 + mi*16 + g;
        int r1 = r0 + 8;
        float bi0 = bo[r0], bi1 = bo[r1];
        #pragma unroll
        for(int ni = 0; ni < 4; ni++){
            int nc = n0 + warp_n*32 + ni*8 + tg*2;
            *(__nv_bfloat162*)&g_integr[(size_t)(b*CC+r0)*HW + nc] =
                pk2(acc[mi][ni][0] + bi0, acc[mi][ni][1] + bi0);
            *(__nv_bfloat162*)&g_integr[(size_t)(b*CC+r1)*HW + nc] =
                pk2(acc[mi][ni][2] + bi1, acc[mi][ni][3] + bi1);
        }
    }
}

// ---------------- stage 7: 3x3 conv as GEMM (K=2304, r-major) ------------------
__device__ __forceinline__ void gatherB_conv(uint4 rv[2], int b, int it, int n0, int tid){
    int r = it >> 3;
    int c0 = (it & 7) * 32;
    int kh = (r * 11) >> 5;
    int dw = (r - kh*3) - 1;
    int dh = kh - 1;
    #pragma unroll
    for(int i = 0; i < 2; i++){
        int id = tid + i*256;
        int krow = id >> 4, u = id & 15;
        const __nv_bfloat16* src = g_integr + (size_t)(b*CC + c0 + krow)*HW;
        int p0 = n0 + u*8;
        int h = p0 >> 6, w0 = p0 & 63;
        int hh = h + dh;
        uint4 out = make_uint4(0u,0u,0u,0u);
        if((unsigned)hh < 64u){
            const __nv_bfloat16* rp = src + hh*64 + w0;
            if(dw == 0){
                out = *(const uint4*)rp;
            } else if(dw > 0){
                uint4 v = *(const uint4*)rp;
                uint32_t nx = (w0 < 56) ? *(const uint32_t*)(rp + 8) : 0u;
                out.x = __byte_perm(v.x, v.y, 0x5432);
                out.y = __byte_perm(v.y, v.z, 0x5432);
                out.z = __byte_perm(v.z, v.w, 0x5432);
                out.w = __byte_perm(v.w, nx,  0x5432);
            } else {
                uint4 v = *(const uint4*)rp;
                uint32_t pv = (w0 > 0) ? *(const uint32_t*)(rp - 2) : 0u;
                out.x = __byte_perm(pv,  v.x, 0x5432);
                out.y = __byte_perm(v.x, v.y, 0x5432);
                out.z = __byte_perm(v.y, v.z, 0x5432);
                out.w = __byte_perm(v.z, v.w, 0x5432);
            }
        }
        rv[i] = out;
    }
}
__device__ __forceinline__ void stsB_conv(uint32_t* smBbuf, const uint4 rv[2], int tid){
    #pragma unroll
    for(int i = 0; i < 2; i++){
        int id = tid + i*256;
        int k = id >> 4, u = id & 15;
        int widx = k*64 + ((u ^ (k&7)) << 2);
        *(uint4*)&smBbuf[widx] = rv[i];
    }
}

__global__ __launch_bounds__(256,2) void k_convT()
{
    int b = blockIdx.z;
    int m0 = blockIdx.y * 128;
    int n0 = blockIdx.x * 128;
    const int lda = CC*9;
    const int nk = (CC*9)/32;   // 72

    GEMM_PRE();
    cpA(AsB,        g_cw_bf + (size_t)m0*lda + 0,  lda, tid); CP_COMMIT();
    cpA(AsB + 8192, g_cw_bf + (size_t)m0*lda + 32, lda, tid); CP_COMMIT();
    {
        uint4 rv[2];
        gatherB_conv(rv, b, 0, n0, tid);
        stsB_conv(smB[0], rv, tid);
    }
    const __nv_bfloat16* srcA = g_cw_bf + (size_t)m0*lda + 64;
    int cb = 0, st = 2;
    for(int it = 0; it < nk; it++){
        if(it + 1 < nk) { CP_WAIT1(); } else { CP_WAIT0(); }
        __syncthreads();
        if(it + 2 < nk){
            cpA(AsB + st*8192, srcA, lda, tid);
            CP_COMMIT();
            srcA += 32;
        }
        uint4 rv[2];
        if(it + 1 < nk) gatherB_conv(rv, b, it+1, n0, tid);
        chunk_mma(AsB + cb*8192, BsB + cb*8192, acc, warp_m, warp_n, lane);
        if(it + 1 < nk) stsB_conv(smB[(it+1) == 3 || (it+1) == 6 ? (it+1)%3 : (it+1)%3], rv, tid);
        cb = (cb == 2) ? 0 : cb + 1;
        st = (st == 2) ? 0 : st + 1;
    }
    #pragma unroll
    for(int mi = 0; mi < 4; mi++){
        int r0 = m0 + warp_m*64 + mi*16 + g;
        int r1 = r0 + 8;
        float bi0 = g_cb[r0], bi1 = g_cb[r1];
        #pragma unroll
        for(int ni = 0; ni < 4; ni++){
            int nc = n0 + warp_n*32 + ni*8 + tg*2;
            *(__nv_bfloat162*)&g_y2[(size_t)(b*CC+r0)*HW + nc] =
                pk2(gelu_f(acc[mi][ni][0] + bi0), gelu_f(acc[mi][ni][1] + bi0));
            *(__nv_bfloat162*)&g_y2[(size_t)(b*CC+r1)*HW + nc] =
                pk2(gelu_f(acc[mi][ni][2] + bi1), gelu_f(acc[mi][ni][3] + bi1));
        }
    }
}

// ---------------- stage 8: final 1x1 + residual --------------------------------
__global__ __launch_bounds__(256,2) void k_finalT(const float* __restrict__ b2,
                                                  const float* __restrict__ x,
                                                  float* __restrict__ out)
{
    int b = blockIdx.z;
    int m0 = blockIdx.y * 128;
    int n0 = blockIdx.x * 128;
    int lda = CC; size_t strideB = HW;

    GEMM_PRE();
    #define APTR(it) (g_w2_bf + (size_t)m0*CC + (it)*32)
    #define BPTR(it) (g_y2 + (size_t)(b*CC + (it)*32)*HW + n0)
    GEMM_LOOP(8, APTR, BPTR)
    #undef APTR
    #undef BPTR
    #pragma unroll
    for(int mi = 0; mi < 4; mi++){
        int r0 = m0 + warp_m*64 + mi*16 + g;
        int r1 = r0 + 8;
        float bi0 = b2[r0], bi1 = b2[r1];
        const float* res0 = x + (size_t)((1*BB+b)*CC + r0)*HW;
        const float* res1 = x + (size_t)((1*BB+b)*CC + r1)*HW;
        #pragma unroll
        for(int ni = 0; ni < 4; ni++){
            int nc = n0 + warp_n*32 + ni*8 + tg*2;
            float2 a0 = *(const float2*)&res0[nc];
            float2 a1 = *(const float2*)&res1[nc];
            float2 o0, o1;
            o0.x = acc[mi][ni][0] + bi0 + a0.x; o0.y = acc[mi][ni][1] + bi0 + a0.y;
            o1.x = acc[mi][ni][2] + bi1 + a1.x; o1.y = acc[mi][ni][3] + bi1 + a1.y;
            *(float2*)&out[(size_t)(b*CC+r0)*HW + nc] = o0;
            *(float2*)&out[(size_t)(b*CC+r1)*HW + nc] = o1;
        }
    }
}

// ---------------- launcher ------------------------------------------------------
extern "C" void kernel_launch(void* const* d_in, const int* in_sizes, int n_in,
                              void* d_out, int out_size)
{
    (void)in_sizes; (void)n_in; (void)out_size;
    const float* x   = (const float*)d_in[0];
    const float* Wq  = (const float*)d_in[1];
    const float* bq  = (const float*)d_in[2];
    const float* bnq = (const float*)d_in[3];
    const float* Wk_ = (const float*)d_in[4];
    const float* bk_ = (const float*)d_in[5];
    const float* bnk = (const float*)d_in[6];
    const float* Wv  = (const float*)d_in[7];
    const float* bv  = (const float*)d_in[8];
    const float* bnv = (const float*)d_in[9];
    const float* iw1 = (const float*)d_in[10];
    const float* ib1 = (const float*)d_in[11];
    const float* iw2 = (const float*)d_in[12];
    const float* ib2 = (const float*)d_in[13];
    const float* aiw = (const float*)d_in[14];
    const float* aib = (const float*)d_in[15];
    const float* aow = (const float*)d_in[16];
    const float* aob = (const float*)d_in[17];
    const float* cw  = (const float*)d_in[18];
    const float* cb1 = (const float*)d_in[19];
    const float* cbn = (const float*)d_in[20];
    const float* w2  = (const float*)d_in[21];
    const float* b2  = (const float*)d_in[22];
    float* out = (float*)d_out;

    k_cvt<<<3072 + 1472, 256>>>(Wq, Wk_, Wv, aiw, aow, cw, w2, bnq, bnk, bnv, cbn, x);
    k_fold<<<1, 256>>>(bq, bnq, bk_, bnk, bv, bnv, cb1, cbn);
    k_imp<<<32, 256>>>(iw1, ib1, iw2, ib2);
    k_projT<<<dim3(32,2,36), 256>>>();
    k_attninT<<<dim3(32,2,36), 256>>>(aib);
    k_attn<<<dim3(32,8), 256>>>();
    k_outT<<<dim3(32,2,4), 256>>>(aob);
    k_convT<<<dim3(32,2,4), 256>>>();
    k_finalT<<<dim3(32,2,4), 256>>>(b2, x, out);
}